// round 6
// baseline (speedup 1.0000x reference)
#include <cuda_runtime.h>
#include <cuda_bf16.h>
#include <math.h>
#include <stdint.h>

// Problem constants
#define BATCH   32
#define HDIM    64
#define WDIM    64
#define CDIM    256
#define WS      8
#define SS      4
#define HEADS   8
#define HD      32
#define WS2     64
#define NWPI    64
#define NWIN    2048
#define QKV_N   768
#define MROWS   (NWIN * WS2)          // 131072
#define SCALE   0.17677669529663687f

// Scratch
__device__ __nv_bfloat16 g_qkv_hi[(size_t)MROWS * QKV_N];
__device__ __nv_bfloat16 g_qkv_lo[(size_t)MROWS * QKV_N];
__device__ __nv_bfloat16 g_x_hi[(size_t)MROWS * CDIM];      // window-ordered, split
__device__ __nv_bfloat16 g_x_lo[(size_t)MROWS * CDIM];
__device__ __nv_bfloat16 g_att_hi[(size_t)MROWS * CDIM];
__device__ __nv_bfloat16 g_att_lo[(size_t)MROWS * CDIM];
__device__ __nv_bfloat16 g_wq_hi[QKV_N * CDIM];             // [n][k]
__device__ __nv_bfloat16 g_wq_lo[QKV_N * CDIM];
__device__ __nv_bfloat16 g_wo_hi[CDIM * CDIM];
__device__ __nv_bfloat16 g_wo_lo[CDIM * CDIM];

// GEMM smem: 3 stages x {A 16KB, B 16KB}; rows are [32 hi | 32 lo] bf16 = 128B
#define STAGE_BYTES 32768
#define OFF_B       16384
#define OFF_BIAS    98304
#define SMEM_GEMM   98816
#define NCHUNK      8                 // K = 256 in chunks of 32

// Attention smem: per local head {Q 8K | K 8K | V 8K}, then pe
#define ATT_HSTRIDE 24576
#define ATT_PE_OFF  49152
#define SMEM_ATT    51200

__device__ __forceinline__ int global_row(int win, int m) {
    int b  = win >> 6;
    int wi = win & 63;
    int wy = wi >> 3, wx = wi & 7;
    int ty = m >> 3,  tx = m & 7;
    int sy = (wy * 8 + ty + SS) & 63;
    int sx = (wx * 8 + tx + SS) & 63;
    return b * (HDIM * WDIM) + sy * WDIM + sx;
}

__device__ __forceinline__ uint32_t smem_u32(const void* p) {
    uint32_t a;
    asm("{ .reg .u64 t; cvta.to.shared.u64 t, %1; cvt.u32.u64 %0, t; }" : "=r"(a) : "l"(p));
    return a;
}
__device__ __forceinline__ uint32_t sw128(uint32_t off) {
    return off ^ ((off >> 3) & 0x70);
}
__device__ __forceinline__ void cp16(uint32_t dst, const void* src) {
    asm volatile("cp.async.cg.shared.global [%0], [%1], 16;" :: "r"(dst), "l"(src));
}
__device__ __forceinline__ void ldsm4(uint32_t* r, uint32_t addr) {
    asm volatile("ldmatrix.sync.aligned.m8n8.x4.shared.b16 {%0,%1,%2,%3}, [%4];"
                 : "=r"(r[0]), "=r"(r[1]), "=r"(r[2]), "=r"(r[3]) : "r"(addr));
}
__device__ __forceinline__ void ldsm2(uint32_t* r, uint32_t addr) {
    asm volatile("ldmatrix.sync.aligned.m8n8.x2.shared.b16 {%0,%1}, [%2];"
                 : "=r"(r[0]), "=r"(r[1]) : "r"(addr));
}
__device__ __forceinline__ void ldsm2t(uint32_t* r, uint32_t addr) {
    asm volatile("ldmatrix.sync.aligned.m8n8.x2.trans.shared.b16 {%0,%1}, [%2];"
                 : "=r"(r[0]), "=r"(r[1]) : "r"(addr));
}
__device__ __forceinline__ void mma16816(float* c, const uint32_t* a, const uint32_t* b) {
    asm volatile(
        "mma.sync.aligned.m16n8k16.row.col.f32.bf16.bf16.f32 "
        "{%0,%1,%2,%3}, {%4,%5,%6,%7}, {%8,%9}, {%0,%1,%2,%3};"
        : "+f"(c[0]), "+f"(c[1]), "+f"(c[2]), "+f"(c[3])
        : "r"(a[0]), "r"(a[1]), "r"(a[2]), "r"(a[3]), "r"(b[0]), "r"(b[1]));
}

// split 2 floats -> packed hi bf16x2 and lo bf16x2
__device__ __forceinline__ void split2(float a, float b, uint32_t& h, uint32_t& l) {
    __nv_bfloat162 hh = __float22bfloat162_rn(make_float2(a, b));
    float2 hf = __bfloat1622float2(hh);
    __nv_bfloat162 ll = __float22bfloat162_rn(make_float2(a - hf.x, b - hf.y));
    h = *(uint32_t*)&hh;
    l = *(uint32_t*)&ll;
}

// ---------------------------------------------------------------------------
// 3-stage pipelined bf16 hi/lo HMMA GEMM. 128x128 CTA tile, K=256, chunks of 32.
// grid = (nb, mt): adjacent CTAs share the A tile (L2 reuse).
// SPLIT: emit bf16 hi/lo outputs; else fp32. SCATTER: shift-scatter rows.
// ---------------------------------------------------------------------------
template<int NT, bool SCATTER, bool SPLIT>
__global__ __launch_bounds__(256, 2) void gemm_mma(
    const __nv_bfloat16* __restrict__ Ah, const __nv_bfloat16* __restrict__ Al,
    const __nv_bfloat16* __restrict__ Bh, const __nv_bfloat16* __restrict__ Bl,
    const float* __restrict__ bias, float* __restrict__ out,
    __nv_bfloat16* __restrict__ oh, __nv_bfloat16* __restrict__ ol)
{
    extern __shared__ char smem[];
    const uint32_t sb = smem_u32(smem);
    const int tid = threadIdx.x, l = tid & 31, wid = tid >> 5;
    const int nb = blockIdx.x, mt = blockIdx.y;
    const int wm = wid >> 2, wn = wid & 3;

    float* bias_s = (float*)(smem + OFF_BIAS);
    if (tid < 128) bias_s[tid] = bias[nb * 128 + tid];

    // cp geometry: 2 threads per row; thread covers 2 hi chunks + 2 lo chunks
    const int row  = tid >> 1;
    const int half = tid & 1;
    const uint32_t smA0 = sw128(row * 128 + half * 32);
    const uint32_t smA1 = sw128(row * 128 + half * 32 + 16);
    const uint32_t smA2 = sw128(row * 128 + 64 + half * 32);
    const uint32_t smA3 = sw128(row * 128 + 64 + half * 32 + 16);

    const __nv_bfloat16* pAh = Ah + (size_t)(mt * 128 + row) * CDIM + half * 16;
    const __nv_bfloat16* pAl = Al + (size_t)(mt * 128 + row) * CDIM + half * 16;
    const __nv_bfloat16* pBh = Bh + (size_t)(nb * 128 + row) * CDIM + half * 16;
    const __nv_bfloat16* pBl = Bl + (size_t)(nb * 128 + row) * CDIM + half * 16;

    // ldmatrix lane geometry
    const int sub  = l >> 3;
    const int arl  = wm * 64 + (sub & 1) * 8 + (l & 7);
    const int acb  = (sub >> 1) * 16;
    const int lb   = l & 15;
    const int brl  = wn * 32 + (lb & 7);
    const int bcb  = (lb >> 3) * 16;

    float acc[4][4][4];
    #pragma unroll
    for (int i = 0; i < 4; i++)
        #pragma unroll
        for (int j = 0; j < 4; j++)
            #pragma unroll
            for (int r = 0; r < 4; r++) acc[i][j][r] = 0.f;

    // prologue: prefetch chunks 0, 1
    #pragma unroll
    for (int c = 0; c < 2; c++) {
        uint32_t buf = sb + c * STAGE_BYTES;
        int ko = c * 32;
        cp16(buf + smA0, pAh + ko);
        cp16(buf + smA1, pAh + ko + 8);
        cp16(buf + smA2, pAl + ko);
        cp16(buf + smA3, pAl + ko + 8);
        cp16(buf + OFF_B + smA0, pBh + ko);
        cp16(buf + OFF_B + smA1, pBh + ko + 8);
        cp16(buf + OFF_B + smA2, pBl + ko);
        cp16(buf + OFF_B + smA3, pBl + ko + 8);
        asm volatile("cp.async.commit_group;");
    }

    #pragma unroll
    for (int k = 0; k < NCHUNK; k++) {
        if (k < NCHUNK - 1) asm volatile("cp.async.wait_group 1;");
        else                asm volatile("cp.async.wait_group 0;");
        __syncthreads();

        if (k + 2 < NCHUNK) {
            uint32_t buf = sb + ((k + 2) % 3) * STAGE_BYTES;
            int ko = (k + 2) * 32;
            cp16(buf + smA0, pAh + ko);
            cp16(buf + smA1, pAh + ko + 8);
            cp16(buf + smA2, pAl + ko);
            cp16(buf + smA3, pAl + ko + 8);
            cp16(buf + OFF_B + smA0, pBh + ko);
            cp16(buf + OFF_B + smA1, pBh + ko + 8);
            cp16(buf + OFF_B + smA2, pBl + ko);
            cp16(buf + OFF_B + smA3, pBl + ko + 8);
            asm volatile("cp.async.commit_group;");
        }

        const uint32_t cb = sb + (k % 3) * STAGE_BYTES;
        #pragma unroll
        for (int k16 = 0; k16 < 2; k16++) {
            uint32_t Bhf[4][2], Blf[4][2];
            #pragma unroll
            for (int ni = 0; ni < 4; ni++) {
                uint32_t r = (brl + ni * 8) * 128 + k16 * 32 + bcb;
                ldsm2(Bhf[ni], cb + OFF_B + sw128(r));
                ldsm2(Blf[ni], cb + OFF_B + sw128(r + 64));
            }
            #pragma unroll
            for (int mi = 0; mi < 4; mi++) {
                uint32_t r = (arl + mi * 16) * 128 + k16 * 32 + acb;
                uint32_t Ahf[4], Alf[4];
                ldsm4(Ahf, cb + sw128(r));
                ldsm4(Alf, cb + sw128(r + 64));
                #pragma unroll
                for (int ni = 0; ni < 4; ni++) {
                    mma16816(acc[mi][ni], Ahf, Bhf[ni]);
                    mma16816(acc[mi][ni], Ahf, Blf[ni]);
                    mma16816(acc[mi][ni], Alf, Bhf[ni]);
                }
            }
        }
    }
    __syncthreads();

    // epilogue via smem stage
    float* stage = (float*)smem;
    #pragma unroll
    for (int mi = 0; mi < 4; mi++)
        #pragma unroll
        for (int ni = 0; ni < 4; ni++) {
            int r   = wm * 64 + mi * 16 + (l >> 2);
            int col = wn * 32 + ni * 8 + (l & 3) * 2;
            *(float2*)&stage[r * 132 + col]       = make_float2(acc[mi][ni][0], acc[mi][ni][1]);
            *(float2*)&stage[(r + 8) * 132 + col] = make_float2(acc[mi][ni][2], acc[mi][ni][3]);
        }
    __syncthreads();

    #pragma unroll
    for (int it = 0; it < 16; it++) {
        int idx = it * 256 + tid;
        int r  = idx >> 5, c4 = (idx & 31) * 4;
        float4 o;
        o.x = stage[r * 132 + c4 + 0] + bias_s[c4 + 0];
        o.y = stage[r * 132 + c4 + 1] + bias_s[c4 + 1];
        o.z = stage[r * 132 + c4 + 2] + bias_s[c4 + 2];
        o.w = stage[r * 132 + c4 + 3] + bias_s[c4 + 3];
        int lrow = mt * 128 + r;
        int orow = SCATTER ? global_row(lrow >> 6, lrow & 63) : lrow;
        size_t off = (size_t)orow * NT + nb * 128 + c4;
        if (SPLIT) {
            uint32_t h0, l0, h1, l1;
            split2(o.x, o.y, h0, l0);
            split2(o.z, o.w, h1, l1);
            *(uint2*)(oh + off) = make_uint2(h0, h1);
            *(uint2*)(ol + off) = make_uint2(l0, l1);
        } else {
            *(float4*)(out + off) = o;
        }
    }
}

// ---------------------------------------------------------------------------
// Pre-pass: gather x into window order and split to bf16 hi/lo
// ---------------------------------------------------------------------------
__global__ __launch_bounds__(256) void convert_x(const float* __restrict__ x) {
    const int win = blockIdx.x;
    const int tid = threadIdx.x;
    #pragma unroll
    for (int i = 0; i < 16; i++) {
        int idx4 = i * 256 + tid;
        int row  = idx4 >> 6;
        int c4   = idx4 & 63;
        int grow = global_row(win, row);
        float4 v = *(const float4*)(x + (size_t)grow * CDIM + c4 * 4);
        uint32_t h0, h1, l0, l1;
        split2(v.x, v.y, h0, l0);
        split2(v.z, v.w, h1, l1);
        size_t o = ((size_t)win * WS2 + row) * CDIM + c4 * 4;
        *(uint2*)(g_x_hi + o) = make_uint2(h0, h1);
        *(uint2*)(g_x_lo + o) = make_uint2(l0, l1);
    }
}

__global__ void convert_w(const float* __restrict__ wq, const float* __restrict__ wo) {
    int n = blockIdx.x, k = threadIdx.x;
    if (n < QKV_N) {
        float v = wq[k * QKV_N + n];
        __nv_bfloat16 h = __float2bfloat16(v);
        g_wq_hi[n * CDIM + k] = h;
        g_wq_lo[n * CDIM + k] = __float2bfloat16(v - __bfloat162float(h));
    } else {
        int n2 = n - QKV_N;
        float v = wo[k * CDIM + n2];
        __nv_bfloat16 h = __float2bfloat16(v);
        g_wo_hi[n2 * CDIM + k] = h;
        g_wo_lo[n2 * CDIM + k] = __float2bfloat16(v - __bfloat162float(h));
    }
}

// ---------------------------------------------------------------------------
// HMMA attention. Block = (2 heads, window), 4 warps; warp = 32 q x 64 k.
// ---------------------------------------------------------------------------
__global__ __launch_bounds__(128) void attn_mma(
    const __nv_bfloat16* __restrict__ qh_g, const __nv_bfloat16* __restrict__ ql_g,
    const float* __restrict__ pos)
{
    extern __shared__ char smem[];
    const uint32_t sb = smem_u32(smem);
    const int tid = threadIdx.x, l = tid & 31, wid = tid >> 5;
    const int hg  = blockIdx.x;
    const int win = blockIdx.y;
    const int wi  = win & 63, wy = wi >> 3, wx = wi & 7;

    #pragma unroll
    for (int i = 0; i < 24; i++) {
        int idx  = i * 128 + tid;
        int hl   = idx >= 1536;
        int rem  = idx - hl * 1536;
        int mat  = rem >> 9;
        int rem2 = rem & 511;
        int row  = rem2 >> 3;
        int ch   = rem2 & 7;
        int isHi = ch < 4;
        int c16  = ch & 3;
        uint32_t dst = sb + hl * ATT_HSTRIDE + mat * 8192
                     + sw128(row * 128 + (isHi ? 0 : 64) + c16 * 16);
        const __nv_bfloat16* src = (isHi ? qh_g : ql_g)
            + (size_t)(win * 64 + row) * QKV_N + (hg * 2 + hl) * 32 + mat * 256 + c16 * 8;
        cp16(dst, src);
    }
    asm volatile("cp.async.commit_group;");
    float* pe_s = (float*)(smem + ATT_PE_OFF);
    for (int i = tid; i < 450; i += 128) {
        int hh = i >= 225;
        pe_s[i] = pos[(hg * 2 + hh) * 225 + (i - hh * 225)];
    }
    asm volatile("cp.async.wait_group 0;");
    __syncthreads();

    const int hl = wid >> 1;
    const int w  = wid & 1;
    const uint32_t QB = sb + hl * ATT_HSTRIDE;
    const uint32_t KB = QB + 8192;
    const uint32_t VB = QB + 16384;
    const float* pe = pe_s + hl * 225;

    const int sub = l >> 3;
    const int arl = (sub & 1) * 8 + (l & 7);
    const int acb = (sub >> 1) * 16;
    const int lb  = l & 15;
    const int brl = lb & 7;
    const int bcb = (lb >> 3) * 16;

    float sc[2][8][4];
    #pragma unroll
    for (int mi = 0; mi < 2; mi++)
        #pragma unroll
        for (int ni = 0; ni < 8; ni++)
            #pragma unroll
            for (int r = 0; r < 4; r++) sc[mi][ni][r] = 0.f;

    #pragma unroll
    for (int k16 = 0; k16 < 2; k16++) {
        uint32_t Ah[2][4], Al[2][4];
        #pragma unroll
        for (int mi = 0; mi < 2; mi++) {
            uint32_t r = (w * 32 + mi * 16 + arl) * 128 + k16 * 32 + acb;
            ldsm4(Ah[mi], QB + sw128(r));
            ldsm4(Al[mi], QB + sw128(r + 64));
        }
        #pragma unroll
        for (int ni = 0; ni < 8; ni++) {
            uint32_t Bh[2], Bl[2];
            uint32_t r = (ni * 8 + brl) * 128 + k16 * 32 + bcb;
            ldsm2(Bh, KB + sw128(r));
            ldsm2(Bl, KB + sw128(r + 64));
            #pragma unroll
            for (int mi = 0; mi < 2; mi++) {
                mma16816(sc[mi][ni], Ah[mi], Bh);
                mma16816(sc[mi][ni], Ah[mi], Bl);
                mma16816(sc[mi][ni], Al[mi], Bh);
            }
        }
    }

    float rinv[2][2];
    #pragma unroll
    for (int mi = 0; mi < 2; mi++)
        #pragma unroll
        for (int rr = 0; rr < 2; rr++) {
            int r  = w * 32 + mi * 16 + rr * 8 + (l >> 2);
            int qy = r >> 3, qx = r & 7;
            int gy = wy * 8 + qy, gx = wx * 8 + qx;
            int rq = (gy < 56 ? 0 : (gy < 60 ? 1 : 2)) * 3 + (gx < 56 ? 0 : (gx < 60 ? 1 : 2));
            float m = -1e30f;
            #pragma unroll
            for (int ni = 0; ni < 8; ni++)
                #pragma unroll
                for (int j = 0; j < 2; j++) {
                    int c  = ni * 8 + (l & 3) * 2 + j;
                    int ky = c >> 3, kx = c & 7;
                    int hy = wy * 8 + ky, hx = wx * 8 + kx;
                    int rk = (hy < 56 ? 0 : (hy < 60 ? 1 : 2)) * 3 + (hx < 56 ? 0 : (hx < 60 ? 1 : 2));
                    float v = sc[mi][ni][rr * 2 + j];
                    v = (rk == rq) ? v * SCALE + pe[(qy - ky + 7) * 15 + (qx - kx + 7)] : -1e30f;
                    sc[mi][ni][rr * 2 + j] = v;
                    m = fmaxf(m, v);
                }
            m = fmaxf(m, __shfl_xor_sync(0xffffffffu, m, 1));
            m = fmaxf(m, __shfl_xor_sync(0xffffffffu, m, 2));
            float s = 0.f;
            #pragma unroll
            for (int ni = 0; ni < 8; ni++)
                #pragma unroll
                for (int j = 0; j < 2; j++) {
                    float e = __expf(sc[mi][ni][rr * 2 + j] - m);
                    sc[mi][ni][rr * 2 + j] = e;
                    s += e;
                }
            s += __shfl_xor_sync(0xffffffffu, s, 1);
            s += __shfl_xor_sync(0xffffffffu, s, 2);
            rinv[mi][rr] = 1.0f / s;
        }

    __syncthreads();

    const uint32_t PH = QB + w * 4096;
    const uint32_t PL = KB + w * 4096;
    char* smc = (char*)smem;
    #pragma unroll
    for (int mi = 0; mi < 2; mi++)
        #pragma unroll
        for (int rr = 0; rr < 2; rr++) {
            int lr = mi * 16 + rr * 8 + (l >> 2);
            #pragma unroll
            for (int ni = 0; ni < 8; ni++) {
                uint32_t h, lo;
                split2(sc[mi][ni][rr * 2], sc[mi][ni][rr * 2 + 1], h, lo);
                uint32_t off = sw128(lr * 128 + ni * 16 + (l & 3) * 4);
                *(uint32_t*)(smc + (PH - sb) + off) = h;
                *(uint32_t*)(smc + (PL - sb) + off) = lo;
            }
        }
    __syncwarp();

    float o[2][4][4];
    #pragma unroll
    for (int mi = 0; mi < 2; mi++)
        #pragma unroll
        for (int nj = 0; nj < 4; nj++)
            #pragma unroll
            for (int r = 0; r < 4; r++) o[mi][nj][r] = 0.f;

    #pragma unroll
    for (int k16 = 0; k16 < 4; k16++) {
        uint32_t Ph[2][4], Pl[2][4];
        #pragma unroll
        for (int mi = 0; mi < 2; mi++) {
            uint32_t r = (mi * 16 + arl) * 128 + k16 * 32 + acb;
            ldsm4(Ph[mi], PH + sw128(r));
            ldsm4(Pl[mi], PL + sw128(r));
        }
        #pragma unroll
        for (int nj = 0; nj < 4; nj++) {
            uint32_t Vh[2], Vl[2];
            uint32_t r = (k16 * 16 + lb) * 128 + nj * 16;
            ldsm2t(Vh, VB + sw128(r));
            ldsm2t(Vl, VB + sw128(r + 64));
            #pragma unroll
            for (int mi = 0; mi < 2; mi++) {
                mma16816(o[mi][nj], Ph[mi], Vh);
                mma16816(o[mi][nj], Ph[mi], Vl);
                mma16816(o[mi][nj], Pl[mi], Vh);
            }
        }
    }

    const int head = hg * 2 + hl;
    #pragma unroll
    for (int mi = 0; mi < 2; mi++)
        #pragma unroll
        for (int rr = 0; rr < 2; rr++) {
            int r = w * 32 + mi * 16 + rr * 8 + (l >> 2);
            float inv = rinv[mi][rr];
            size_t rowoff = (size_t)(win * 64 + r) * CDIM + head * 32;
            #pragma unroll
            for (int nj = 0; nj < 4; nj++) {
                int c = nj * 8 + (l & 3) * 2;
                uint32_t h, lo;
                split2(o[mi][nj][rr * 2] * inv, o[mi][nj][rr * 2 + 1] * inv, h, lo);
                *(uint32_t*)(g_att_hi + rowoff + c) = h;
                *(uint32_t*)(g_att_lo + rowoff + c) = lo;
            }
        }
}

// ---------------------------------------------------------------------------
extern "C" void kernel_launch(void* const* d_in, const int* in_sizes, int n_in,
                              void* d_out, int out_size) {
    const float* x     = (const float*)d_in[0];
    const float* w_qkv = (const float*)d_in[1];
    const float* b_qkv = (const float*)d_in[2];
    const float* w_out = (const float*)d_in[3];
    const float* b_out = (const float*)d_in[4];
    const float* pos   = (const float*)d_in[5];
    float* out = (float*)d_out;

    __nv_bfloat16 *qh, *ql, *xh, *xl, *ah, *al, *wqh, *wql, *woh, *wol;
    cudaGetSymbolAddress((void**)&qh,  g_qkv_hi);
    cudaGetSymbolAddress((void**)&ql,  g_qkv_lo);
    cudaGetSymbolAddress((void**)&xh,  g_x_hi);
    cudaGetSymbolAddress((void**)&xl,  g_x_lo);
    cudaGetSymbolAddress((void**)&ah,  g_att_hi);
    cudaGetSymbolAddress((void**)&al,  g_att_lo);
    cudaGetSymbolAddress((void**)&wqh, g_wq_hi);
    cudaGetSymbolAddress((void**)&wql, g_wq_lo);
    cudaGetSymbolAddress((void**)&woh, g_wo_hi);
    cudaGetSymbolAddress((void**)&wol, g_wo_lo);

    cudaFuncSetAttribute(gemm_mma<QKV_N, false, true>,
                         cudaFuncAttributeMaxDynamicSharedMemorySize, SMEM_GEMM);
    cudaFuncSetAttribute(gemm_mma<CDIM, true, false>,
                         cudaFuncAttributeMaxDynamicSharedMemorySize, SMEM_GEMM);
    cudaFuncSetAttribute(attn_mma,
                         cudaFuncAttributeMaxDynamicSharedMemorySize, SMEM_ATT);

    convert_w<<<1024, 256>>>(w_qkv, w_out);
    convert_x<<<NWIN, 256>>>(x);
    gemm_mma<QKV_N, false, true><<<dim3(6, 1024), 256, SMEM_GEMM>>>(
        xh, xl, wqh, wql, b_qkv, nullptr, qh, ql);
    attn_mma<<<dim3(4, NWIN), 128, SMEM_ATT>>>(qh, ql, pos);
    gemm_mma<CDIM, true, false><<<dim3(2, 1024), 256, SMEM_GEMM>>>(
        ah, al, woh, wol, b_out, out, nullptr, nullptr);
}

// round 7
// speedup vs baseline: 1.2468x; 1.2468x over previous
#include <cuda_runtime.h>
#include <cuda_bf16.h>
#include <math.h>
#include <stdint.h>

// Problem constants
#define BATCH   32
#define HDIM    64
#define WDIM    64
#define CDIM    256
#define WS      8
#define SS      4
#define HEADS   8
#define HD      32
#define WS2     64
#define NWPI    64
#define NWIN    2048
#define QKV_N   768
#define MROWS   (NWIN * WS2)          // 131072
#define SCALE   0.17677669529663687f

// Scratch
__device__ __nv_bfloat16 g_qkv_hi[(size_t)MROWS * QKV_N];
__device__ __nv_bfloat16 g_qkv_lo[(size_t)MROWS * QKV_N];
__device__ __nv_bfloat16 g_x_hi[(size_t)MROWS * CDIM];      // window-ordered, split
__device__ __nv_bfloat16 g_x_lo[(size_t)MROWS * CDIM];
__device__ __nv_bfloat16 g_att_hi[(size_t)MROWS * CDIM];
__device__ __nv_bfloat16 g_att_lo[(size_t)MROWS * CDIM];
__device__ __nv_bfloat16 g_wq_hi[QKV_N * CDIM];             // [n][k]
__device__ __nv_bfloat16 g_wq_lo[QKV_N * CDIM];
__device__ __nv_bfloat16 g_wo_hi[CDIM * CDIM];
__device__ __nv_bfloat16 g_wo_lo[CDIM * CDIM];
__device__ float g_bias[HEADS * 4 * WS2 * WS2];             // bias+mask per window class

// GEMM smem: 2 stages x {AH 8K, AL 8K, BH 8K, BL 8K}
#define STAGE_BYTES 32768
#define SOFF_AL     8192
#define SOFF_BH     16384
#define SOFF_BL     24576
#define OFF_BIAS    65536
#define SMEM_GEMM   65792

// Attention smem: per local head {Q 8K | K 8K | V 8K}
#define ATT_HSTRIDE 24576
#define SMEM_ATT    49152

__device__ __forceinline__ int global_row(int win, int m) {
    int b  = win >> 6;
    int wi = win & 63;
    int wy = wi >> 3, wx = wi & 7;
    int ty = m >> 3,  tx = m & 7;
    int sy = (wy * 8 + ty + SS) & 63;
    int sx = (wx * 8 + tx + SS) & 63;
    return b * (HDIM * WDIM) + sy * WDIM + sx;
}

__device__ __forceinline__ uint32_t smem_u32(const void* p) {
    uint32_t a;
    asm("{ .reg .u64 t; cvta.to.shared.u64 t, %1; cvt.u32.u64 %0, t; }" : "=r"(a) : "l"(p));
    return a;
}
__device__ __forceinline__ uint32_t sw128(uint32_t off) {
    return off ^ ((off >> 3) & 0x70);
}
__device__ __forceinline__ void cp16(uint32_t dst, const void* src) {
    asm volatile("cp.async.cg.shared.global [%0], [%1], 16;" :: "r"(dst), "l"(src));
}
__device__ __forceinline__ void ldsm4(uint32_t* r, uint32_t addr) {
    asm volatile("ldmatrix.sync.aligned.m8n8.x4.shared.b16 {%0,%1,%2,%3}, [%4];"
                 : "=r"(r[0]), "=r"(r[1]), "=r"(r[2]), "=r"(r[3]) : "r"(addr));
}
__device__ __forceinline__ void ldsm2(uint32_t* r, uint32_t addr) {
    asm volatile("ldmatrix.sync.aligned.m8n8.x2.shared.b16 {%0,%1}, [%2];"
                 : "=r"(r[0]), "=r"(r[1]) : "r"(addr));
}
__device__ __forceinline__ void ldsm2t(uint32_t* r, uint32_t addr) {
    asm volatile("ldmatrix.sync.aligned.m8n8.x2.trans.shared.b16 {%0,%1}, [%2];"
                 : "=r"(r[0]), "=r"(r[1]) : "r"(addr));
}
__device__ __forceinline__ void mma16816(float* c, const uint32_t* a, const uint32_t* b) {
    asm volatile(
        "mma.sync.aligned.m16n8k16.row.col.f32.bf16.bf16.f32 "
        "{%0,%1,%2,%3}, {%4,%5,%6,%7}, {%8,%9}, {%0,%1,%2,%3};"
        : "+f"(c[0]), "+f"(c[1]), "+f"(c[2]), "+f"(c[3])
        : "r"(a[0]), "r"(a[1]), "r"(a[2]), "r"(a[3]), "r"(b[0]), "r"(b[1]));
}

__device__ __forceinline__ void split2(float a, float b, uint32_t& h, uint32_t& l) {
    __nv_bfloat162 hh = __float22bfloat162_rn(make_float2(a, b));
    float2 hf = __bfloat1622float2(hh);
    __nv_bfloat162 ll = __float22bfloat162_rn(make_float2(a - hf.x, b - hf.y));
    h = *(uint32_t*)&hh;
    l = *(uint32_t*)&ll;
}

// ---------------------------------------------------------------------------
// 64x64-tile bf16 hi/lo HMMA GEMM, 128 threads, 3 CTAs/SM, 2-stage pipeline.
// grid = (nb, mt): adjacent CTAs share the A tile (L2 reuse).
// ---------------------------------------------------------------------------
template<int NT, bool SCATTER, bool SPLIT>
__global__ __launch_bounds__(128, 3) void gemm_mma(
    const __nv_bfloat16* __restrict__ Ah, const __nv_bfloat16* __restrict__ Al,
    const __nv_bfloat16* __restrict__ Bh, const __nv_bfloat16* __restrict__ Bl,
    const float* __restrict__ bias, float* __restrict__ out,
    __nv_bfloat16* __restrict__ oh, __nv_bfloat16* __restrict__ ol)
{
    extern __shared__ char smem[];
    const uint32_t sb = smem_u32(smem);
    const int tid = threadIdx.x, l = tid & 31, wid = tid >> 5;
    const int nb = blockIdx.x, mt = blockIdx.y;
    const int wm = wid >> 1, wn = wid & 1;

    float* bias_s = (float*)(smem + OFF_BIAS);
    if (tid < 64) bias_s[tid] = bias[nb * 64 + tid];

    // cp.async geometry: 16 rows per pass, 8x16B chunks per row
    const int crow = tid >> 3;          // 0..15
    const int cc   = tid & 7;
    uint32_t smo[4];
    #pragma unroll
    for (int i = 0; i < 4; i++)
        smo[i] = sw128((crow + i * 16) * 128 + cc * 16);

    const __nv_bfloat16* pAh = Ah + (size_t)(mt * 64 + crow) * CDIM + cc * 8;
    const __nv_bfloat16* pAl = Al + (size_t)(mt * 64 + crow) * CDIM + cc * 8;
    const __nv_bfloat16* pBh = Bh + (size_t)(nb * 64 + crow) * CDIM + cc * 8;
    const __nv_bfloat16* pBl = Bl + (size_t)(nb * 64 + crow) * CDIM + cc * 8;

    // ldmatrix lane geometry
    const int sub = l >> 3;
    const int arl = wm * 32 + (sub & 1) * 8 + (l & 7);
    const int acb = (sub >> 1) * 16;
    const int lb  = l & 15;
    const int brl = wn * 32 + (lb & 7);
    const int bcb = (lb >> 3) * 16;

    float acc[2][4][4];
    #pragma unroll
    for (int i = 0; i < 2; i++)
        #pragma unroll
        for (int j = 0; j < 4; j++)
            #pragma unroll
            for (int r = 0; r < 4; r++) acc[i][j][r] = 0.f;

    // prefetch chunk 0 into stage 0
    #pragma unroll
    for (int i = 0; i < 4; i++) {
        size_t g = (size_t)(i * 16) * CDIM;
        cp16(sb + smo[i],           pAh + g);
        cp16(sb + SOFF_AL + smo[i], pAl + g);
        cp16(sb + SOFF_BH + smo[i], pBh + g);
        cp16(sb + SOFF_BL + smo[i], pBl + g);
    }
    asm volatile("cp.async.commit_group;");

    #pragma unroll
    for (int k = 0; k < 4; k++) {
        asm volatile("cp.async.wait_group 0;");
        __syncthreads();
        if (k < 3) {
            uint32_t buf = sb + ((k + 1) & 1) * STAGE_BYTES;
            int ko = (k + 1) * 64;
            #pragma unroll
            for (int i = 0; i < 4; i++) {
                size_t g = (size_t)(i * 16) * CDIM + ko;
                cp16(buf + smo[i],           pAh + g);
                cp16(buf + SOFF_AL + smo[i], pAl + g);
                cp16(buf + SOFF_BH + smo[i], pBh + g);
                cp16(buf + SOFF_BL + smo[i], pBl + g);
            }
            asm volatile("cp.async.commit_group;");
        }

        const uint32_t cb = sb + (k & 1) * STAGE_BYTES;
        #pragma unroll
        for (int k16 = 0; k16 < 4; k16++) {
            const int k0b = k16 * 32;
            uint32_t Bhf[4][2], Blf[4][2];
            #pragma unroll
            for (int ni = 0; ni < 4; ni++) {
                uint32_t r = (brl + ni * 8) * 128 + k0b + bcb;
                ldsm2(Bhf[ni], cb + SOFF_BH + sw128(r));
                ldsm2(Blf[ni], cb + SOFF_BL + sw128(r));
            }
            #pragma unroll
            for (int mi = 0; mi < 2; mi++) {
                uint32_t r = (arl + mi * 16) * 128 + k0b + acb;
                uint32_t Ahf[4], Alf[4];
                ldsm4(Ahf, cb + sw128(r));
                ldsm4(Alf, cb + SOFF_AL + sw128(r));
                #pragma unroll
                for (int ni = 0; ni < 4; ni++) {
                    mma16816(acc[mi][ni], Ahf, Bhf[ni]);
                    mma16816(acc[mi][ni], Ahf, Blf[ni]);
                    mma16816(acc[mi][ni], Alf, Bhf[ni]);
                }
            }
        }
        __syncthreads();
    }

    // epilogue via smem stage (64 x 68 floats = 17.4KB, fits in stage area)
    float* stage = (float*)smem;
    #pragma unroll
    for (int mi = 0; mi < 2; mi++)
        #pragma unroll
        for (int ni = 0; ni < 4; ni++) {
            int r   = wm * 32 + mi * 16 + (l >> 2);
            int col = wn * 32 + ni * 8 + (l & 3) * 2;
            *(float2*)&stage[r * 68 + col]       = make_float2(acc[mi][ni][0], acc[mi][ni][1]);
            *(float2*)&stage[(r + 8) * 68 + col] = make_float2(acc[mi][ni][2], acc[mi][ni][3]);
        }
    __syncthreads();

    #pragma unroll
    for (int it = 0; it < 8; it++) {
        int idx = it * 128 + tid;
        int r  = idx >> 4, c4 = (idx & 15) * 4;
        float4 o;
        o.x = stage[r * 68 + c4 + 0] + bias_s[c4 + 0];
        o.y = stage[r * 68 + c4 + 1] + bias_s[c4 + 1];
        o.z = stage[r * 68 + c4 + 2] + bias_s[c4 + 2];
        o.w = stage[r * 68 + c4 + 3] + bias_s[c4 + 3];
        int lrow = mt * 64 + r;
        int orow = SCATTER ? global_row(lrow >> 6, lrow & 63) : lrow;
        size_t off = (size_t)orow * NT + nb * 64 + c4;
        if (SPLIT) {
            uint32_t h0, l0, h1, l1;
            split2(o.x, o.y, h0, l0);
            split2(o.z, o.w, h1, l1);
            *(uint2*)(oh + off) = make_uint2(h0, h1);
            *(uint2*)(ol + off) = make_uint2(l0, l1);
        } else {
            *(float4*)(out + off) = o;
        }
    }
}

// ---------------------------------------------------------------------------
// Pre-pass: gather x into window order and split to bf16 hi/lo
// ---------------------------------------------------------------------------
__global__ __launch_bounds__(256) void convert_x(const float* __restrict__ x) {
    const int win = blockIdx.x;
    const int tid = threadIdx.x;
    #pragma unroll
    for (int i = 0; i < 16; i++) {
        int idx4 = i * 256 + tid;
        int row  = idx4 >> 6;
        int c4   = idx4 & 63;
        int grow = global_row(win, row);
        float4 v = *(const float4*)(x + (size_t)grow * CDIM + c4 * 4);
        uint32_t h0, h1, l0, l1;
        split2(v.x, v.y, h0, l0);
        split2(v.z, v.w, h1, l1);
        size_t o = ((size_t)win * WS2 + row) * CDIM + c4 * 4;
        *(uint2*)(g_x_hi + o) = make_uint2(h0, h1);
        *(uint2*)(g_x_lo + o) = make_uint2(l0, l1);
    }
}

__global__ void convert_w(const float* __restrict__ wq, const float* __restrict__ wo) {
    int n = blockIdx.x, k = threadIdx.x;
    if (n < QKV_N) {
        float v = wq[k * QKV_N + n];
        __nv_bfloat16 h = __float2bfloat16(v);
        g_wq_hi[n * CDIM + k] = h;
        g_wq_lo[n * CDIM + k] = __float2bfloat16(v - __bfloat162float(h));
    } else {
        int n2 = n - QKV_N;
        float v = wo[k * CDIM + n2];
        __nv_bfloat16 h = __float2bfloat16(v);
        g_wo_hi[n2 * CDIM + k] = h;
        g_wo_lo[n2 * CDIM + k] = __float2bfloat16(v - __bfloat162float(h));
    }
}

// ---------------------------------------------------------------------------
// Build bias+mask table: [head][class][64q][64k]; class = interior/right/bot/corner
// ---------------------------------------------------------------------------
__global__ void build_bias(const float* __restrict__ pos) {
    int h = blockIdx.x >> 2, cls = blockIdx.x & 3;
    int wy = (cls & 2) ? 7 : 0, wx = (cls & 1) ? 7 : 0;
    for (int it = 0; it < 16; it++) {
        int idx = it * 256 + threadIdx.x;
        int q = idx >> 6, k = idx & 63;
        int qy = q >> 3, qx = q & 7, ky = k >> 3, kx = k & 7;
        int gy = wy * 8 + qy, gx = wx * 8 + qx;
        int hy = wy * 8 + ky, hx = wx * 8 + kx;
        int rq = (gy < 56 ? 0 : (gy < 60 ? 1 : 2)) * 3 + (gx < 56 ? 0 : (gx < 60 ? 1 : 2));
        int rk = (hy < 56 ? 0 : (hy < 60 ? 1 : 2)) * 3 + (hx < 56 ? 0 : (hx < 60 ? 1 : 2));
        float v = (rq == rk) ? pos[h * 225 + (qy - ky + 7) * 15 + (qx - kx + 7)] : -1e30f;
        g_bias[(size_t)(h * 4 + cls) * 4096 + idx] = v;
    }
}

// ---------------------------------------------------------------------------
// HMMA attention. Block = (2 heads, window), 4 warps; warp = 32 q x 64 k.
// Bias+mask from precomputed table (L2-resident).
// ---------------------------------------------------------------------------
__global__ __launch_bounds__(128) void attn_mma(
    const __nv_bfloat16* __restrict__ qh_g, const __nv_bfloat16* __restrict__ ql_g)
{
    extern __shared__ char smem[];
    const uint32_t sb = smem_u32(smem);
    const int tid = threadIdx.x, l = tid & 31, wid = tid >> 5;
    const int hg  = blockIdx.x;
    const int win = blockIdx.y;
    const int wi  = win & 63, wy = wi >> 3, wx = wi & 7;
    const int cls = ((wy == 7) ? 2 : 0) | ((wx == 7) ? 1 : 0);

    #pragma unroll
    for (int i = 0; i < 24; i++) {
        int idx  = i * 128 + tid;
        int hl   = idx >= 1536;
        int rem  = idx - hl * 1536;
        int mat  = rem >> 9;
        int rem2 = rem & 511;
        int row  = rem2 >> 3;
        int ch   = rem2 & 7;
        int isHi = ch < 4;
        int c16  = ch & 3;
        uint32_t dst = sb + hl * ATT_HSTRIDE + mat * 8192
                     + sw128(row * 128 + (isHi ? 0 : 64) + c16 * 16);
        const __nv_bfloat16* src = (isHi ? qh_g : ql_g)
            + (size_t)(win * 64 + row) * QKV_N + (hg * 2 + hl) * 32 + mat * 256 + c16 * 8;
        cp16(dst, src);
    }
    asm volatile("cp.async.commit_group;");
    asm volatile("cp.async.wait_group 0;");
    __syncthreads();

    const int hl = wid >> 1;
    const int w  = wid & 1;
    const uint32_t QB = sb + hl * ATT_HSTRIDE;
    const uint32_t KB = QB + 8192;
    const uint32_t VB = QB + 16384;
    const float* T = g_bias + (size_t)((hg * 2 + hl) * 4 + cls) * 4096;

    const int sub = l >> 3;
    const int arl = (sub & 1) * 8 + (l & 7);
    const int acb = (sub >> 1) * 16;
    const int lb  = l & 15;
    const int brl = lb & 7;
    const int bcb = (lb >> 3) * 16;

    float sc[2][8][4];
    #pragma unroll
    for (int mi = 0; mi < 2; mi++)
        #pragma unroll
        for (int ni = 0; ni < 8; ni++)
            #pragma unroll
            for (int r = 0; r < 4; r++) sc[mi][ni][r] = 0.f;

    #pragma unroll
    for (int k16 = 0; k16 < 2; k16++) {
        uint32_t Ah[2][4], Al[2][4];
        #pragma unroll
        for (int mi = 0; mi < 2; mi++) {
            uint32_t r = (w * 32 + mi * 16 + arl) * 128 + k16 * 32 + acb;
            ldsm4(Ah[mi], QB + sw128(r));
            ldsm4(Al[mi], QB + sw128(r + 64));
        }
        #pragma unroll
        for (int ni = 0; ni < 8; ni++) {
            uint32_t Bh[2], Bl[2];
            uint32_t r = (ni * 8 + brl) * 128 + k16 * 32 + bcb;
            ldsm2(Bh, KB + sw128(r));
            ldsm2(Bl, KB + sw128(r + 64));
            #pragma unroll
            for (int mi = 0; mi < 2; mi++) {
                mma16816(sc[mi][ni], Ah[mi], Bh);
                mma16816(sc[mi][ni], Ah[mi], Bl);
                mma16816(sc[mi][ni], Al[mi], Bh);
            }
        }
    }

    float rinv[2][2];
    #pragma unroll
    for (int mi = 0; mi < 2; mi++)
        #pragma unroll
        for (int rr = 0; rr < 2; rr++) {
            int r = w * 32 + mi * 16 + rr * 8 + (l >> 2);
            const float* Tr = T + r * 64 + (l & 3) * 2;
            float m = -1e30f;
            #pragma unroll
            for (int ni = 0; ni < 8; ni++) {
                float2 b2 = *(const float2*)(Tr + ni * 8);
                float v0 = sc[mi][ni][rr * 2]     * SCALE + b2.x;
                float v1 = sc[mi][ni][rr * 2 + 1] * SCALE + b2.y;
                sc[mi][ni][rr * 2]     = v0;
                sc[mi][ni][rr * 2 + 1] = v1;
                m = fmaxf(m, fmaxf(v0, v1));
            }
            m = fmaxf(m, __shfl_xor_sync(0xffffffffu, m, 1));
            m = fmaxf(m, __shfl_xor_sync(0xffffffffu, m, 2));
            float s = 0.f;
            #pragma unroll
            for (int ni = 0; ni < 8; ni++)
                #pragma unroll
                for (int j = 0; j < 2; j++) {
                    float e = __expf(sc[mi][ni][rr * 2 + j] - m);
                    sc[mi][ni][rr * 2 + j] = e;
                    s += e;
                }
            s += __shfl_xor_sync(0xffffffffu, s, 1);
            s += __shfl_xor_sync(0xffffffffu, s, 2);
            rinv[mi][rr] = 1.0f / s;
        }

    __syncthreads();

    const uint32_t PH = QB + w * 4096;
    const uint32_t PL = KB + w * 4096;
    char* smc = (char*)smem;
    #pragma unroll
    for (int mi = 0; mi < 2; mi++)
        #pragma unroll
        for (int rr = 0; rr < 2; rr++) {
            int lr = mi * 16 + rr * 8 + (l >> 2);
            #pragma unroll
            for (int ni = 0; ni < 8; ni++) {
                uint32_t h, lo;
                split2(sc[mi][ni][rr * 2], sc[mi][ni][rr * 2 + 1], h, lo);
                uint32_t off = sw128(lr * 128 + ni * 16 + (l & 3) * 4);
                *(uint32_t*)(smc + (PH - sb) + off) = h;
                *(uint32_t*)(smc + (PL - sb) + off) = lo;
            }
        }
    __syncwarp();

    float o[2][4][4];
    #pragma unroll
    for (int mi = 0; mi < 2; mi++)
        #pragma unroll
        for (int nj = 0; nj < 4; nj++)
            #pragma unroll
            for (int r = 0; r < 4; r++) o[mi][nj][r] = 0.f;

    #pragma unroll
    for (int k16 = 0; k16 < 4; k16++) {
        uint32_t Ph[2][4], Pl[2][4];
        #pragma unroll
        for (int mi = 0; mi < 2; mi++) {
            uint32_t r = (mi * 16 + arl) * 128 + k16 * 32 + acb;
            ldsm4(Ph[mi], PH + sw128(r));
            ldsm4(Pl[mi], PL + sw128(r));
        }
        #pragma unroll
        for (int nj = 0; nj < 4; nj++) {
            uint32_t Vh[2], Vl[2];
            uint32_t r = (k16 * 16 + lb) * 128 + nj * 16;
            ldsm2t(Vh, VB + sw128(r));
            ldsm2t(Vl, VB + sw128(r + 64));
            #pragma unroll
            for (int mi = 0; mi < 2; mi++) {
                mma16816(o[mi][nj], Ph[mi], Vh);
                mma16816(o[mi][nj], Ph[mi], Vl);
                mma16816(o[mi][nj], Pl[mi], Vh);
            }
        }
    }

    const int head = hg * 2 + hl;
    #pragma unroll
    for (int mi = 0; mi < 2; mi++)
        #pragma unroll
        for (int rr = 0; rr < 2; rr++) {
            int r = w * 32 + mi * 16 + rr * 8 + (l >> 2);
            float inv = rinv[mi][rr];
            size_t rowoff = (size_t)(win * 64 + r) * CDIM + head * 32;
            #pragma unroll
            for (int nj = 0; nj < 4; nj++) {
                int c = nj * 8 + (l & 3) * 2;
                uint32_t h, lo;
                split2(o[mi][nj][rr * 2] * inv, o[mi][nj][rr * 2 + 1] * inv, h, lo);
                *(uint32_t*)(g_att_hi + rowoff + c) = h;
                *(uint32_t*)(g_att_lo + rowoff + c) = lo;
            }
        }
}

// ---------------------------------------------------------------------------
extern "C" void kernel_launch(void* const* d_in, const int* in_sizes, int n_in,
                              void* d_out, int out_size) {
    const float* x     = (const float*)d_in[0];
    const float* w_qkv = (const float*)d_in[1];
    const float* b_qkv = (const float*)d_in[2];
    const float* w_out = (const float*)d_in[3];
    const float* b_out = (const float*)d_in[4];
    const float* pos   = (const float*)d_in[5];
    float* out = (float*)d_out;

    __nv_bfloat16 *qh, *ql, *xh, *xl, *ah, *al, *wqh, *wql, *woh, *wol;
    cudaGetSymbolAddress((void**)&qh,  g_qkv_hi);
    cudaGetSymbolAddress((void**)&ql,  g_qkv_lo);
    cudaGetSymbolAddress((void**)&xh,  g_x_hi);
    cudaGetSymbolAddress((void**)&xl,  g_x_lo);
    cudaGetSymbolAddress((void**)&ah,  g_att_hi);
    cudaGetSymbolAddress((void**)&al,  g_att_lo);
    cudaGetSymbolAddress((void**)&wqh, g_wq_hi);
    cudaGetSymbolAddress((void**)&wql, g_wq_lo);
    cudaGetSymbolAddress((void**)&woh, g_wo_hi);
    cudaGetSymbolAddress((void**)&wol, g_wo_lo);

    cudaFuncSetAttribute(gemm_mma<QKV_N, false, true>,
                         cudaFuncAttributeMaxDynamicSharedMemorySize, SMEM_GEMM);
    cudaFuncSetAttribute(gemm_mma<CDIM, true, false>,
                         cudaFuncAttributeMaxDynamicSharedMemorySize, SMEM_GEMM);
    cudaFuncSetAttribute(attn_mma,
                         cudaFuncAttributeMaxDynamicSharedMemorySize, SMEM_ATT);

    convert_w<<<1024, 256>>>(w_qkv, w_out);
    build_bias<<<32, 256>>>(pos);
    convert_x<<<NWIN, 256>>>(x);
    gemm_mma<QKV_N, false, true><<<dim3(12, 2048), 128, SMEM_GEMM>>>(
        xh, xl, wqh, wql, b_qkv, nullptr, qh, ql);
    attn_mma<<<dim3(4, NWIN), 128, SMEM_ATT>>>(qh, ql);
    gemm_mma<CDIM, true, false><<<dim3(4, 2048), 128, SMEM_GEMM>>>(
        ah, al, woh, wol, b_out, out, nullptr, nullptr);
}

// round 8
// speedup vs baseline: 1.7263x; 1.3845x over previous
#include <cuda_runtime.h>
#include <cuda_fp16.h>
#include <math.h>
#include <stdint.h>

// Problem constants
#define BATCH   32
#define HDIM    64
#define WDIM    64
#define CDIM    256
#define WS      8
#define SS      4
#define HEADS   8
#define HD      32
#define WS2     64
#define NWPI    64
#define NWIN    2048
#define QKV_N   768
#define MROWS   (NWIN * WS2)          // 131072
#define SCALE   0.17677669529663687f

// Scratch (fp16 activations, fp16 hi/lo weights)
__device__ __half g_qkv_f16[(size_t)MROWS * QKV_N];
__device__ __half g_x_f16[(size_t)MROWS * CDIM];            // window-ordered
__device__ __half g_att_f16[(size_t)MROWS * CDIM];
__device__ __half g_wq_hi[QKV_N * CDIM];                    // [n][k]
__device__ __half g_wq_lo[QKV_N * CDIM];
__device__ __half g_wo_hi[CDIM * CDIM];
__device__ __half g_wo_lo[CDIM * CDIM];
__device__ float g_bias[HEADS * 4 * WS2 * WS2];             // bias+mask per window class

// GEMM smem: 2 stages x {A 8K, BH 8K, BL 8K}
#define STAGE_BYTES 24576
#define SOFF_BH     8192
#define SOFF_BL     16384
#define OFF_BIAS    49152
#define SMEM_GEMM   49408

// Attention smem: Q 8K | K 8K | V 8K  (Q/K reused for P)
#define SMEM_ATT    24576

__device__ __forceinline__ int global_row(int win, int m) {
    int b  = win >> 6;
    int wi = win & 63;
    int wy = wi >> 3, wx = wi & 7;
    int ty = m >> 3,  tx = m & 7;
    int sy = (wy * 8 + ty + SS) & 63;
    int sx = (wx * 8 + tx + SS) & 63;
    return b * (HDIM * WDIM) + sy * WDIM + sx;
}

__device__ __forceinline__ uint32_t smem_u32(const void* p) {
    uint32_t a;
    asm("{ .reg .u64 t; cvta.to.shared.u64 t, %1; cvt.u32.u64 %0, t; }" : "=r"(a) : "l"(p));
    return a;
}
__device__ __forceinline__ uint32_t sw128(uint32_t off) {
    return off ^ ((off >> 3) & 0x70);
}
__device__ __forceinline__ void cp16(uint32_t dst, const void* src) {
    asm volatile("cp.async.cg.shared.global [%0], [%1], 16;" :: "r"(dst), "l"(src));
}
__device__ __forceinline__ void ldsm4(uint32_t* r, uint32_t addr) {
    asm volatile("ldmatrix.sync.aligned.m8n8.x4.shared.b16 {%0,%1,%2,%3}, [%4];"
                 : "=r"(r[0]), "=r"(r[1]), "=r"(r[2]), "=r"(r[3]) : "r"(addr));
}
__device__ __forceinline__ void ldsm2(uint32_t* r, uint32_t addr) {
    asm volatile("ldmatrix.sync.aligned.m8n8.x2.shared.b16 {%0,%1}, [%2];"
                 : "=r"(r[0]), "=r"(r[1]) : "r"(addr));
}
__device__ __forceinline__ void ldsm2t(uint32_t* r, uint32_t addr) {
    asm volatile("ldmatrix.sync.aligned.m8n8.x2.trans.shared.b16 {%0,%1}, [%2];"
                 : "=r"(r[0]), "=r"(r[1]) : "r"(addr));
}
__device__ __forceinline__ void mma16816(float* c, const uint32_t* a, const uint32_t* b) {
    asm volatile(
        "mma.sync.aligned.m16n8k16.row.col.f32.f16.f16.f32 "
        "{%0,%1,%2,%3}, {%4,%5,%6,%7}, {%8,%9}, {%0,%1,%2,%3};"
        : "+f"(c[0]), "+f"(c[1]), "+f"(c[2]), "+f"(c[3])
        : "r"(a[0]), "r"(a[1]), "r"(a[2]), "r"(a[3]), "r"(b[0]), "r"(b[1]));
}

__device__ __forceinline__ uint32_t pack_h2(float a, float b) {
    __half2 h = __floats2half2_rn(a, b);
    return *(uint32_t*)&h;
}
__device__ __forceinline__ void split2h(float a, float b, uint32_t& h, uint32_t& l) {
    __half2 hh = __floats2half2_rn(a, b);
    float2 hf = __half22float2(hh);
    __half2 ll = __floats2half2_rn(a - hf.x, b - hf.y);
    h = *(uint32_t*)&hh;
    l = *(uint32_t*)&ll;
}

// ---------------------------------------------------------------------------
// 64x64-tile fp16 HMMA GEMM: A single fp16, B split hi/lo, 2 passes.
// 128 threads, 3 CTAs/SM, 2-stage pipeline. grid = (nb, mt).
// ---------------------------------------------------------------------------
template<int NT, bool SCATTER, bool OUTF16>
__global__ __launch_bounds__(128, 3) void gemm_mma(
    const __half* __restrict__ Af,
    const __half* __restrict__ Bh, const __half* __restrict__ Bl,
    const float* __restrict__ bias, float* __restrict__ out,
    __half* __restrict__ oh)
{
    extern __shared__ char smem[];
    const uint32_t sb = smem_u32(smem);
    const int tid = threadIdx.x, l = tid & 31, wid = tid >> 5;
    const int nb = blockIdx.x, mt = blockIdx.y;
    const int wm = wid >> 1, wn = wid & 1;

    float* bias_s = (float*)(smem + OFF_BIAS);
    if (tid < 64) bias_s[tid] = bias[nb * 64 + tid];

    const int crow = tid >> 3;          // 0..15
    const int cc   = tid & 7;
    uint32_t smo[4];
    #pragma unroll
    for (int i = 0; i < 4; i++)
        smo[i] = sw128((crow + i * 16) * 128 + cc * 16);

    const __half* pA  = Af + (size_t)(mt * 64 + crow) * CDIM + cc * 8;
    const __half* pBh = Bh + (size_t)(nb * 64 + crow) * CDIM + cc * 8;
    const __half* pBl = Bl + (size_t)(nb * 64 + crow) * CDIM + cc * 8;

    const int sub = l >> 3;
    const int arl = wm * 32 + (sub & 1) * 8 + (l & 7);
    const int acb = (sub >> 1) * 16;
    const int lb  = l & 15;
    const int brl = wn * 32 + (lb & 7);
    const int bcb = (lb >> 3) * 16;

    float acc[2][4][4];
    #pragma unroll
    for (int i = 0; i < 2; i++)
        #pragma unroll
        for (int j = 0; j < 4; j++)
            #pragma unroll
            for (int r = 0; r < 4; r++) acc[i][j][r] = 0.f;

    // prefetch chunk 0
    #pragma unroll
    for (int i = 0; i < 4; i++) {
        size_t g = (size_t)(i * 16) * CDIM;
        cp16(sb + smo[i],           pA  + g);
        cp16(sb + SOFF_BH + smo[i], pBh + g);
        cp16(sb + SOFF_BL + smo[i], pBl + g);
    }
    asm volatile("cp.async.commit_group;");

    #pragma unroll
    for (int k = 0; k < 4; k++) {
        asm volatile("cp.async.wait_group 0;");
        __syncthreads();
        if (k < 3) {
            uint32_t buf = sb + ((k + 1) & 1) * STAGE_BYTES;
            int ko = (k + 1) * 64;
            #pragma unroll
            for (int i = 0; i < 4; i++) {
                size_t g = (size_t)(i * 16) * CDIM + ko;
                cp16(buf + smo[i],           pA  + g);
                cp16(buf + SOFF_BH + smo[i], pBh + g);
                cp16(buf + SOFF_BL + smo[i], pBl + g);
            }
            asm volatile("cp.async.commit_group;");
        }

        const uint32_t cb = sb + (k & 1) * STAGE_BYTES;
        #pragma unroll
        for (int k16 = 0; k16 < 4; k16++) {
            const int k0b = k16 * 32;
            uint32_t Bhf[4][2], Blf[4][2];
            #pragma unroll
            for (int ni = 0; ni < 4; ni++) {
                uint32_t r = (brl + ni * 8) * 128 + k0b + bcb;
                ldsm2(Bhf[ni], cb + SOFF_BH + sw128(r));
                ldsm2(Blf[ni], cb + SOFF_BL + sw128(r));
            }
            #pragma unroll
            for (int mi = 0; mi < 2; mi++) {
                uint32_t r = (arl + mi * 16) * 128 + k0b + acb;
                uint32_t Ahf[4];
                ldsm4(Ahf, cb + sw128(r));
                #pragma unroll
                for (int ni = 0; ni < 4; ni++) {
                    mma16816(acc[mi][ni], Ahf, Bhf[ni]);
                    mma16816(acc[mi][ni], Ahf, Blf[ni]);
                }
            }
        }
        __syncthreads();
    }

    // epilogue via smem stage
    float* stage = (float*)smem;
    #pragma unroll
    for (int mi = 0; mi < 2; mi++)
        #pragma unroll
        for (int ni = 0; ni < 4; ni++) {
            int r   = wm * 32 + mi * 16 + (l >> 2);
            int col = wn * 32 + ni * 8 + (l & 3) * 2;
            *(float2*)&stage[r * 68 + col]       = make_float2(acc[mi][ni][0], acc[mi][ni][1]);
            *(float2*)&stage[(r + 8) * 68 + col] = make_float2(acc[mi][ni][2], acc[mi][ni][3]);
        }
    __syncthreads();

    #pragma unroll
    for (int it = 0; it < 8; it++) {
        int idx = it * 128 + tid;
        int r  = idx >> 4, c4 = (idx & 15) * 4;
        float4 o;
        o.x = stage[r * 68 + c4 + 0] + bias_s[c4 + 0];
        o.y = stage[r * 68 + c4 + 1] + bias_s[c4 + 1];
        o.z = stage[r * 68 + c4 + 2] + bias_s[c4 + 2];
        o.w = stage[r * 68 + c4 + 3] + bias_s[c4 + 3];
        int lrow = mt * 64 + r;
        int orow = SCATTER ? global_row(lrow >> 6, lrow & 63) : lrow;
        size_t off = (size_t)orow * NT + nb * 64 + c4;
        if (OUTF16) {
            *(uint2*)(oh + off) = make_uint2(pack_h2(o.x, o.y), pack_h2(o.z, o.w));
        } else {
            *(float4*)(out + off) = o;
        }
    }
}

// ---------------------------------------------------------------------------
// Pre-pass: gather x into window order, convert to fp16
// ---------------------------------------------------------------------------
__global__ __launch_bounds__(256) void convert_x(const float* __restrict__ x) {
    const int win = blockIdx.x;
    const int tid = threadIdx.x;
    #pragma unroll
    for (int i = 0; i < 16; i++) {
        int idx4 = i * 256 + tid;
        int row  = idx4 >> 6;
        int c4   = idx4 & 63;
        int grow = global_row(win, row);
        float4 v = *(const float4*)(x + (size_t)grow * CDIM + c4 * 4);
        size_t o = ((size_t)win * WS2 + row) * CDIM + c4 * 4;
        *(uint2*)(g_x_f16 + o) = make_uint2(pack_h2(v.x, v.y), pack_h2(v.z, v.w));
    }
}

__global__ void convert_w(const float* __restrict__ wq, const float* __restrict__ wo) {
    int n = blockIdx.x, k = threadIdx.x;
    if (n < QKV_N) {
        float v = wq[k * QKV_N + n];
        __half h = __float2half_rn(v);
        g_wq_hi[n * CDIM + k] = h;
        g_wq_lo[n * CDIM + k] = __float2half_rn(v - __half2float(h));
    } else {
        int n2 = n - QKV_N;
        float v = wo[k * CDIM + n2];
        __half h = __float2half_rn(v);
        g_wo_hi[n2 * CDIM + k] = h;
        g_wo_lo[n2 * CDIM + k] = __float2half_rn(v - __half2float(h));
    }
}

// ---------------------------------------------------------------------------
// Build bias+mask table: [head][class][64q][64k]
// ---------------------------------------------------------------------------
__global__ void build_bias(const float* __restrict__ pos) {
    int h = blockIdx.x >> 2, cls = blockIdx.x & 3;
    int wy = (cls & 2) ? 7 : 0, wx = (cls & 1) ? 7 : 0;
    for (int it = 0; it < 16; it++) {
        int idx = it * 256 + threadIdx.x;
        int q = idx >> 6, k = idx & 63;
        int qy = q >> 3, qx = q & 7, ky = k >> 3, kx = k & 7;
        int gy = wy * 8 + qy, gx = wx * 8 + qx;
        int hy = wy * 8 + ky, hx = wx * 8 + kx;
        int rq = (gy < 56 ? 0 : (gy < 60 ? 1 : 2)) * 3 + (gx < 56 ? 0 : (gx < 60 ? 1 : 2));
        int rk = (hy < 56 ? 0 : (hy < 60 ? 1 : 2)) * 3 + (hx < 56 ? 0 : (hx < 60 ? 1 : 2));
        float v = (rq == rk) ? pos[h * 225 + (qy - ky + 7) * 15 + (qx - kx + 7)] : -1e30f;
        g_bias[(size_t)(h * 4 + cls) * 4096 + idx] = v;
    }
}

// ---------------------------------------------------------------------------
// fp16 HMMA attention. Block = (2 heads, window), 4 warps; warp = 32q x 64k.
// Q/K/V single fp16, dual-head packed in 128B rows. P single fp16 over Q/K.
// ---------------------------------------------------------------------------
__global__ __launch_bounds__(128) void attn_mma(const __half* __restrict__ qkv)
{
    extern __shared__ char smem[];
    const uint32_t sb = smem_u32(smem);
    const int tid = threadIdx.x, l = tid & 31, wid = tid >> 5;
    const int hg  = blockIdx.x;
    const int win = blockIdx.y;
    const int wi  = win & 63, wy = wi >> 3, wx = wi & 7;
    const int cls = ((wy == 7) ? 2 : 0) | ((wx == 7) ? 1 : 0);

    // stage Q/K/V: 3 mats x 64 rows x [head0 64B | head1 64B]
    #pragma unroll
    for (int i = 0; i < 12; i++) {
        int idx  = i * 128 + tid;
        int mat  = idx >> 9;
        int rem  = idx & 511;
        int row  = rem >> 3;
        int ch   = rem & 7;
        int hsel = ch >> 2;
        int c16  = ch & 3;
        uint32_t dst = sb + mat * 8192 + sw128(row * 128 + hsel * 64 + c16 * 16);
        const __half* src = qkv + (size_t)(win * 64 + row) * QKV_N
                          + (hg * 2 + hsel) * 32 + mat * 256 + c16 * 8;
        cp16(dst, src);
    }
    asm volatile("cp.async.commit_group;");
    asm volatile("cp.async.wait_group 0;");
    __syncthreads();

    const int hl = wid >> 1;
    const int w  = wid & 1;
    const uint32_t QB = sb;
    const uint32_t KB = sb + 8192;
    const uint32_t VB = sb + 16384;
    const float* T = g_bias + (size_t)((hg * 2 + hl) * 4 + cls) * 4096;

    const int sub = l >> 3;
    const int arl = (sub & 1) * 8 + (l & 7);
    const int acb = (sub >> 1) * 16;
    const int lb  = l & 15;
    const int brl = lb & 7;
    const int bcb = (lb >> 3) * 16;

    // ---- QK^T single pass ----
    float sc[2][8][4];
    #pragma unroll
    for (int mi = 0; mi < 2; mi++)
        #pragma unroll
        for (int ni = 0; ni < 8; ni++)
            #pragma unroll
            for (int r = 0; r < 4; r++) sc[mi][ni][r] = 0.f;

    #pragma unroll
    for (int k16 = 0; k16 < 2; k16++) {
        uint32_t A[2][4];
        #pragma unroll
        for (int mi = 0; mi < 2; mi++) {
            uint32_t r = (w * 32 + mi * 16 + arl) * 128 + hl * 64 + k16 * 32 + acb;
            ldsm4(A[mi], QB + sw128(r));
        }
        #pragma unroll
        for (int ni = 0; ni < 8; ni++) {
            uint32_t B[2];
            uint32_t r = (ni * 8 + brl) * 128 + hl * 64 + k16 * 32 + bcb;
            ldsm2(B, KB + sw128(r));
            #pragma unroll
            for (int mi = 0; mi < 2; mi++)
                mma16816(sc[mi][ni], A[mi], B);
        }
    }

    // ---- softmax with table bias ----
    float rinv[2][2];
    #pragma unroll
    for (int mi = 0; mi < 2; mi++)
        #pragma unroll
        for (int rr = 0; rr < 2; rr++) {
            int r = w * 32 + mi * 16 + rr * 8 + (l >> 2);
            const float* Tr = T + r * 64 + (l & 3) * 2;
            float m = -1e30f;
            #pragma unroll
            for (int ni = 0; ni < 8; ni++) {
                float2 b2 = *(const float2*)(Tr + ni * 8);
                float v0 = sc[mi][ni][rr * 2]     * SCALE + b2.x;
                float v1 = sc[mi][ni][rr * 2 + 1] * SCALE + b2.y;
                sc[mi][ni][rr * 2]     = v0;
                sc[mi][ni][rr * 2 + 1] = v1;
                m = fmaxf(m, fmaxf(v0, v1));
            }
            m = fmaxf(m, __shfl_xor_sync(0xffffffffu, m, 1));
            m = fmaxf(m, __shfl_xor_sync(0xffffffffu, m, 2));
            float s = 0.f;
            #pragma unroll
            for (int ni = 0; ni < 8; ni++)
                #pragma unroll
                for (int j = 0; j < 2; j++) {
                    float e = __expf(sc[mi][ni][rr * 2 + j] - m);
                    sc[mi][ni][rr * 2 + j] = e;
                    s += e;
                }
            s += __shfl_xor_sync(0xffffffffu, s, 1);
            s += __shfl_xor_sync(0xffffffffu, s, 2);
            rinv[mi][rr] = 1.0f / s;
        }

    // all warps done reading Q/K -> overwrite with P (single fp16)
    __syncthreads();

    const uint32_t PB = sb + (hl * 2 + w) * 4096;   // 32 rows x 128B
    #pragma unroll
    for (int mi = 0; mi < 2; mi++)
        #pragma unroll
        for (int rr = 0; rr < 2; rr++) {
            int lr = mi * 16 + rr * 8 + (l >> 2);
            #pragma unroll
            for (int ni = 0; ni < 8; ni++) {
                uint32_t off = sw128(lr * 128 + ni * 16 + (l & 3) * 4);
                *(uint32_t*)(smem + (PB - sb) + off) =
                    pack_h2(sc[mi][ni][rr * 2], sc[mi][ni][rr * 2 + 1]);
            }
        }
    __syncwarp();

    // ---- P @ V single pass, V via ldmatrix.trans ----
    float o[2][4][4];
    #pragma unroll
    for (int mi = 0; mi < 2; mi++)
        #pragma unroll
        for (int nj = 0; nj < 4; nj++)
            #pragma unroll
            for (int r = 0; r < 4; r++) o[mi][nj][r] = 0.f;

    #pragma unroll
    for (int k16 = 0; k16 < 4; k16++) {
        uint32_t P[2][4];
        #pragma unroll
        for (int mi = 0; mi < 2; mi++) {
            uint32_t r = (mi * 16 + arl) * 128 + k16 * 32 + acb;
            ldsm4(P[mi], PB + sw128(r));
        }
        #pragma unroll
        for (int nj = 0; nj < 4; nj++) {
            uint32_t V[2];
            uint32_t r = (k16 * 16 + lb) * 128 + hl * 64 + nj * 16;
            ldsm2t(V, VB + sw128(r));
            #pragma unroll
            for (int mi = 0; mi < 2; mi++)
                mma16816(o[mi][nj], P[mi], V);
        }
    }

    // ---- epilogue: normalize, store fp16 ----
    const int head = hg * 2 + hl;
    #pragma unroll
    for (int mi = 0; mi < 2; mi++)
        #pragma unroll
        for (int rr = 0; rr < 2; rr++) {
            int r = w * 32 + mi * 16 + rr * 8 + (l >> 2);
            float inv = rinv[mi][rr];
            size_t rowoff = (size_t)(win * 64 + r) * CDIM + head * 32;
            #pragma unroll
            for (int nj = 0; nj < 4; nj++) {
                int c = nj * 8 + (l & 3) * 2;
                *(uint32_t*)(g_att_f16 + rowoff + c) =
                    pack_h2(o[mi][nj][rr * 2] * inv, o[mi][nj][rr * 2 + 1] * inv);
            }
        }
}

// ---------------------------------------------------------------------------
extern "C" void kernel_launch(void* const* d_in, const int* in_sizes, int n_in,
                              void* d_out, int out_size) {
    const float* x     = (const float*)d_in[0];
    const float* w_qkv = (const float*)d_in[1];
    const float* b_qkv = (const float*)d_in[2];
    const float* w_out = (const float*)d_in[3];
    const float* b_out = (const float*)d_in[4];
    const float* pos   = (const float*)d_in[5];
    float* out = (float*)d_out;

    __half *qkv, *xf, *af, *wqh, *wql, *woh, *wol;
    cudaGetSymbolAddress((void**)&qkv, g_qkv_f16);
    cudaGetSymbolAddress((void**)&xf,  g_x_f16);
    cudaGetSymbolAddress((void**)&af,  g_att_f16);
    cudaGetSymbolAddress((void**)&wqh, g_wq_hi);
    cudaGetSymbolAddress((void**)&wql, g_wq_lo);
    cudaGetSymbolAddress((void**)&woh, g_wo_hi);
    cudaGetSymbolAddress((void**)&wol, g_wo_lo);

    cudaFuncSetAttribute(gemm_mma<QKV_N, false, true>,
                         cudaFuncAttributeMaxDynamicSharedMemorySize, SMEM_GEMM);
    cudaFuncSetAttribute(gemm_mma<CDIM, true, false>,
                         cudaFuncAttributeMaxDynamicSharedMemorySize, SMEM_GEMM);
    cudaFuncSetAttribute(attn_mma,
                         cudaFuncAttributeMaxDynamicSharedMemorySize, SMEM_ATT);

    convert_w<<<1024, 256>>>(w_qkv, w_out);
    build_bias<<<32, 256>>>(pos);
    convert_x<<<NWIN, 256>>>(x);
    gemm_mma<QKV_N, false, true><<<dim3(12, 2048), 128, SMEM_GEMM>>>(
        xf, wqh, wql, b_qkv, nullptr, qkv);
    attn_mma<<<dim3(4, NWIN), 128, SMEM_ATT>>>(qkv);
    gemm_mma<CDIM, true, false><<<dim3(4, 2048), 128, SMEM_GEMM>>>(
        af, woh, wol, b_out, out, nullptr);
}

// round 10
// speedup vs baseline: 2.4439x; 1.4157x over previous
#include <cuda_runtime.h>
#include <cuda_fp16.h>
#include <math.h>
#include <stdint.h>

// Problem constants
#define BATCH   32
#define HDIM    64
#define WDIM    64
#define CDIM    256
#define WS      8
#define SS      4
#define HEADS   8
#define HD      32
#define WS2     64
#define NWPI    64
#define NWIN    2048
#define QKV_N   768
#define MROWS   (NWIN * WS2)          // 131072
#define SCALE   0.17677669529663687f

// Scratch (all fp16)
__device__ __half g_qkv_f16[(size_t)MROWS * QKV_N];
__device__ __half g_x_f16[(size_t)MROWS * CDIM];            // window-ordered
__device__ __half g_att_f16[(size_t)MROWS * CDIM];
__device__ __half g_wq[QKV_N * CDIM];                       // [n][k]
__device__ __half g_wo[CDIM * CDIM];
__device__ float g_bias[HEADS * 4 * WS2 * WS2];             // bias+mask per window class

// GEMM smem: 2 stages x {A 8K, B 16K}
#define STAGE_BYTES 24576
#define SOFF_B      8192
#define OFF_BIAS    49152
#define SMEM_GEMM   49664

// Attention smem: Q 8K | K 8K | V 8K  (Q/K reused for P)
#define SMEM_ATT    24576

__device__ __forceinline__ int global_row(int win, int m) {
    int b  = win >> 6;
    int wi = win & 63;
    int wy = wi >> 3, wx = wi & 7;
    int ty = m >> 3,  tx = m & 7;
    int sy = (wy * 8 + ty + SS) & 63;
    int sx = (wx * 8 + tx + SS) & 63;
    return b * (HDIM * WDIM) + sy * WDIM + sx;
}

__device__ __forceinline__ uint32_t smem_u32(const void* p) {
    uint32_t a;
    asm("{ .reg .u64 t; cvta.to.shared.u64 t, %1; cvt.u32.u64 %0, t; }" : "=r"(a) : "l"(p));
    return a;
}
__device__ __forceinline__ uint32_t sw128(uint32_t off) {
    return off ^ ((off >> 3) & 0x70);
}
__device__ __forceinline__ void cp16(uint32_t dst, const void* src) {
    asm volatile("cp.async.cg.shared.global [%0], [%1], 16;" :: "r"(dst), "l"(src));
}
__device__ __forceinline__ void ldsm4(uint32_t* r, uint32_t addr) {
    asm volatile("ldmatrix.sync.aligned.m8n8.x4.shared.b16 {%0,%1,%2,%3}, [%4];"
                 : "=r"(r[0]), "=r"(r[1]), "=r"(r[2]), "=r"(r[3]) : "r"(addr));
}
__device__ __forceinline__ void ldsm2(uint32_t* r, uint32_t addr) {
    asm volatile("ldmatrix.sync.aligned.m8n8.x2.shared.b16 {%0,%1}, [%2];"
                 : "=r"(r[0]), "=r"(r[1]) : "r"(addr));
}
__device__ __forceinline__ void ldsm2t(uint32_t* r, uint32_t addr) {
    asm volatile("ldmatrix.sync.aligned.m8n8.x2.trans.shared.b16 {%0,%1}, [%2];"
                 : "=r"(r[0]), "=r"(r[1]) : "r"(addr));
}
__device__ __forceinline__ void mma16816(float* c, const uint32_t* a, const uint32_t* b) {
    asm volatile(
        "mma.sync.aligned.m16n8k16.row.col.f32.f16.f16.f32 "
        "{%0,%1,%2,%3}, {%4,%5,%6,%7}, {%8,%9}, {%0,%1,%2,%3};"
        : "+f"(c[0]), "+f"(c[1]), "+f"(c[2]), "+f"(c[3])
        : "r"(a[0]), "r"(a[1]), "r"(a[2]), "r"(a[3]), "r"(b[0]), "r"(b[1]));
}

__device__ __forceinline__ uint32_t pack_h2(float a, float b) {
    __half2 h = __floats2half2_rn(a, b);
    return *(uint32_t*)&h;
}

// ---------------------------------------------------------------------------
// 64x128-tile single-pass fp16 HMMA GEMM. 128 threads = 4 warps (2m x 2n),
// warp tile 32x64. 2-stage cp.async pipeline, grid = (nb, mt).
// ---------------------------------------------------------------------------
template<int NT, bool SCATTER, bool OUTF16>
__global__ __launch_bounds__(128, 3) void gemm_mma(
    const __half* __restrict__ Af, const __half* __restrict__ Bf,
    const float* __restrict__ bias, float* __restrict__ out,
    __half* __restrict__ oh)
{
    extern __shared__ char smem[];
    const uint32_t sb = smem_u32(smem);
    const int tid = threadIdx.x, l = tid & 31, wid = tid >> 5;
    const int nb = blockIdx.x, mt = blockIdx.y;
    const int wm = wid >> 1, wn = wid & 1;

    float* bias_s = (float*)(smem + OFF_BIAS);
    bias_s[tid] = bias[nb * 128 + tid];

    // cp.async geometry: chunk row = (tid>>3) + i*16, 16B chunk (tid&7)
    const int crow = tid >> 3;
    const int cc   = tid & 7;
    uint32_t smo[8];
    #pragma unroll
    for (int i = 0; i < 8; i++)
        smo[i] = sw128((crow + i * 16) * 128 + cc * 16);

    const __half* pA = Af + (size_t)(mt * 64 + crow) * CDIM + cc * 8;
    const __half* pB = Bf + (size_t)(nb * 128 + crow) * CDIM + cc * 8;

    // ldmatrix lane geometry
    const int sub = l >> 3;
    const int arl = wm * 32 + (sub & 1) * 8 + (l & 7);  // A row (+mi*16)
    const int acb = (sub >> 1) * 16;                    // A col byte (+k0b)
    const int brl = ((l >> 4) << 3) + (l & 7);          // B row within n16 (+njj*16)
    const int bcb = ((l >> 3) & 1) * 16;                // B col byte (+k0b)

    float acc[2][8][4];
    #pragma unroll
    for (int i = 0; i < 2; i++)
        #pragma unroll
        for (int j = 0; j < 8; j++)
            #pragma unroll
            for (int r = 0; r < 4; r++) acc[i][j][r] = 0.f;

    // prefetch chunk 0
    #pragma unroll
    for (int i = 0; i < 4; i++)
        cp16(sb + smo[i], pA + (size_t)(i * 16) * CDIM);
    #pragma unroll
    for (int i = 0; i < 8; i++)
        cp16(sb + SOFF_B + smo[i], pB + (size_t)(i * 16) * CDIM);
    asm volatile("cp.async.commit_group;");

    #pragma unroll
    for (int k = 0; k < 4; k++) {
        asm volatile("cp.async.wait_group 0;");
        __syncthreads();
        if (k < 3) {
            uint32_t buf = sb + ((k + 1) & 1) * STAGE_BYTES;
            int ko = (k + 1) * 64;
            #pragma unroll
            for (int i = 0; i < 4; i++)
                cp16(buf + smo[i], pA + (size_t)(i * 16) * CDIM + ko);
            #pragma unroll
            for (int i = 0; i < 8; i++)
                cp16(buf + SOFF_B + smo[i], pB + (size_t)(i * 16) * CDIM + ko);
            asm volatile("cp.async.commit_group;");
        }

        const uint32_t cb = sb + (k & 1) * STAGE_BYTES;
        #pragma unroll
        for (int k16 = 0; k16 < 4; k16++) {
            const int k0b = k16 * 32;
            // B: 4x ldsm4, each covers n16 x k16 (2 MMA B-frags)
            uint32_t Bf2[8][2];
            #pragma unroll
            for (int njj = 0; njj < 4; njj++) {
                uint32_t r4[4];
                uint32_t r = (wn * 64 + njj * 16 + brl) * 128 + k0b + bcb;
                ldsm4(r4, cb + SOFF_B + sw128(r));
                Bf2[njj * 2][0]     = r4[0];
                Bf2[njj * 2][1]     = r4[1];
                Bf2[njj * 2 + 1][0] = r4[2];
                Bf2[njj * 2 + 1][1] = r4[3];
            }
            #pragma unroll
            for (int mi = 0; mi < 2; mi++) {
                uint32_t r = (arl + mi * 16) * 128 + k0b + acb;
                uint32_t Afr[4];
                ldsm4(Afr, cb + sw128(r));
                #pragma unroll
                for (int ni = 0; ni < 8; ni++)
                    mma16816(acc[mi][ni], Afr, Bf2[ni]);
            }
        }
        __syncthreads();
    }

    // epilogue via smem stage (64 x 132 floats)
    float* stage = (float*)smem;
    #pragma unroll
    for (int mi = 0; mi < 2; mi++)
        #pragma unroll
        for (int ni = 0; ni < 8; ni++) {
            int r   = wm * 32 + mi * 16 + (l >> 2);
            int col = wn * 64 + ni * 8 + (l & 3) * 2;
            *(float2*)&stage[r * 132 + col]       = make_float2(acc[mi][ni][0], acc[mi][ni][1]);
            *(float2*)&stage[(r + 8) * 132 + col] = make_float2(acc[mi][ni][2], acc[mi][ni][3]);
        }
    __syncthreads();

    #pragma unroll
    for (int it = 0; it < 16; it++) {
        int idx = it * 128 + tid;
        int r  = idx >> 5, c4 = (idx & 31) * 4;
        float4 o;
        o.x = stage[r * 132 + c4 + 0] + bias_s[c4 + 0];
        o.y = stage[r * 132 + c4 + 1] + bias_s[c4 + 1];
        o.z = stage[r * 132 + c4 + 2] + bias_s[c4 + 2];
        o.w = stage[r * 132 + c4 + 3] + bias_s[c4 + 3];
        int lrow = mt * 64 + r;
        int orow = SCATTER ? global_row(lrow >> 6, lrow & 63) : lrow;
        size_t off = (size_t)orow * NT + nb * 128 + c4;
        if (OUTF16) {
            *(uint2*)(oh + off) = make_uint2(pack_h2(o.x, o.y), pack_h2(o.z, o.w));
        } else {
            *(float4*)(out + off) = o;
        }
    }
}

// ---------------------------------------------------------------------------
// Pre-pass: gather x into window order, convert to fp16
// ---------------------------------------------------------------------------
__global__ __launch_bounds__(256) void convert_x(const float* __restrict__ x) {
    const int win = blockIdx.x;
    const int tid = threadIdx.x;
    #pragma unroll
    for (int i = 0; i < 16; i++) {
        int idx4 = i * 256 + tid;
        int row  = idx4 >> 6;
        int c4   = idx4 & 63;
        int grow = global_row(win, row);
        float4 v = *(const float4*)(x + (size_t)grow * CDIM + c4 * 4);
        size_t o = ((size_t)win * WS2 + row) * CDIM + c4 * 4;
        *(uint2*)(g_x_f16 + o) = make_uint2(pack_h2(v.x, v.y), pack_h2(v.z, v.w));
    }
}

__global__ void convert_w(const float* __restrict__ wq, const float* __restrict__ wo) {
    int n = blockIdx.x, k = threadIdx.x;
    if (n < QKV_N) {
        g_wq[n * CDIM + k] = __float2half_rn(wq[k * QKV_N + n]);
    } else {
        int n2 = n - QKV_N;
        g_wo[n2 * CDIM + k] = __float2half_rn(wo[k * CDIM + n2]);
    }
}

// ---------------------------------------------------------------------------
// Build bias+mask table: [head][class][64q][64k]
// ---------------------------------------------------------------------------
__global__ void build_bias(const float* __restrict__ pos) {
    int h = blockIdx.x >> 2, cls = blockIdx.x & 3;
    int wy = (cls & 2) ? 7 : 0, wx = (cls & 1) ? 7 : 0;
    for (int it = 0; it < 16; it++) {
        int idx = it * 256 + threadIdx.x;
        int q = idx >> 6, k = idx & 63;
        int qy = q >> 3, qx = q & 7, ky = k >> 3, kx = k & 7;
        int gy = wy * 8 + qy, gx = wx * 8 + qx;
        int hy = wy * 8 + ky, hx = wx * 8 + kx;
        int rq = (gy < 56 ? 0 : (gy < 60 ? 1 : 2)) * 3 + (gx < 56 ? 0 : (gx < 60 ? 1 : 2));
        int rk = (hy < 56 ? 0 : (hy < 60 ? 1 : 2)) * 3 + (hx < 56 ? 0 : (hx < 60 ? 1 : 2));
        float v = (rq == rk) ? pos[h * 225 + (qy - ky + 7) * 15 + (qx - kx + 7)] : -1e30f;
        g_bias[(size_t)(h * 4 + cls) * 4096 + idx] = v;
    }
}

// ---------------------------------------------------------------------------
// fp16 HMMA attention. Block = (2 heads, window), 4 warps; warp = 32q x 64k.
// ---------------------------------------------------------------------------
__global__ __launch_bounds__(128) void attn_mma(const __half* __restrict__ qkv)
{
    extern __shared__ char smem[];
    const uint32_t sb = smem_u32(smem);
    const int tid = threadIdx.x, l = tid & 31, wid = tid >> 5;
    const int hg  = blockIdx.x;
    const int win = blockIdx.y;
    const int wi  = win & 63, wy = wi >> 3, wx = wi & 7;
    const int cls = ((wy == 7) ? 2 : 0) | ((wx == 7) ? 1 : 0);

    #pragma unroll
    for (int i = 0; i < 12; i++) {
        int idx  = i * 128 + tid;
        int mat  = idx >> 9;
        int rem  = idx & 511;
        int row  = rem >> 3;
        int ch   = rem & 7;
        int hsel = ch >> 2;
        int c16  = ch & 3;
        uint32_t dst = sb + mat * 8192 + sw128(row * 128 + hsel * 64 + c16 * 16);
        const __half* src = qkv + (size_t)(win * 64 + row) * QKV_N
                          + (hg * 2 + hsel) * 32 + mat * 256 + c16 * 8;
        cp16(dst, src);
    }
    asm volatile("cp.async.commit_group;");
    asm volatile("cp.async.wait_group 0;");
    __syncthreads();

    const int hl = wid >> 1;
    const int w  = wid & 1;
    const uint32_t QB = sb;
    const uint32_t KB = sb + 8192;
    const uint32_t VB = sb + 16384;
    const float* T = g_bias + (size_t)((hg * 2 + hl) * 4 + cls) * 4096;

    const int sub = l >> 3;
    const int arl = (sub & 1) * 8 + (l & 7);
    const int acb = (sub >> 1) * 16;
    const int lb  = l & 15;
    const int brl = lb & 7;
    const int bcb = (lb >> 3) * 16;

    float sc[2][8][4];
    #pragma unroll
    for (int mi = 0; mi < 2; mi++)
        #pragma unroll
        for (int ni = 0; ni < 8; ni++)
            #pragma unroll
            for (int r = 0; r < 4; r++) sc[mi][ni][r] = 0.f;

    #pragma unroll
    for (int k16 = 0; k16 < 2; k16++) {
        uint32_t A[2][4];
        #pragma unroll
        for (int mi = 0; mi < 2; mi++) {
            uint32_t r = (w * 32 + mi * 16 + arl) * 128 + hl * 64 + k16 * 32 + acb;
            ldsm4(A[mi], QB + sw128(r));
        }
        #pragma unroll
        for (int ni = 0; ni < 8; ni++) {
            uint32_t B[2];
            uint32_t r = (ni * 8 + brl) * 128 + hl * 64 + k16 * 32 + bcb;
            ldsm2(B, KB + sw128(r));
            #pragma unroll
            for (int mi = 0; mi < 2; mi++)
                mma16816(sc[mi][ni], A[mi], B);
        }
    }

    float rinv[2][2];
    #pragma unroll
    for (int mi = 0; mi < 2; mi++)
        #pragma unroll
        for (int rr = 0; rr < 2; rr++) {
            int r = w * 32 + mi * 16 + rr * 8 + (l >> 2);
            const float* Tr = T + r * 64 + (l & 3) * 2;
            float m = -1e30f;
            #pragma unroll
            for (int ni = 0; ni < 8; ni++) {
                float2 b2 = *(const float2*)(Tr + ni * 8);
                float v0 = sc[mi][ni][rr * 2]     * SCALE + b2.x;
                float v1 = sc[mi][ni][rr * 2 + 1] * SCALE + b2.y;
                sc[mi][ni][rr * 2]     = v0;
                sc[mi][ni][rr * 2 + 1] = v1;
                m = fmaxf(m, fmaxf(v0, v1));
            }
            m = fmaxf(m, __shfl_xor_sync(0xffffffffu, m, 1));
            m = fmaxf(m, __shfl_xor_sync(0xffffffffu, m, 2));
            float s = 0.f;
            #pragma unroll
            for (int ni = 0; ni < 8; ni++)
                #pragma unroll
                for (int j = 0; j < 2; j++) {
                    float e = __expf(sc[mi][ni][rr * 2 + j] - m);
                    sc[mi][ni][rr * 2 + j] = e;
                    s += e;
                }
            s += __shfl_xor_sync(0xffffffffu, s, 1);
            s += __shfl_xor_sync(0xffffffffu, s, 2);
            rinv[mi][rr] = 1.0f / s;
        }

    __syncthreads();

    const uint32_t PB = sb + (hl * 2 + w) * 4096;
    #pragma unroll
    for (int mi = 0; mi < 2; mi++)
        #pragma unroll
        for (int rr = 0; rr < 2; rr++) {
            int lr = mi * 16 + rr * 8 + (l >> 2);
            #pragma unroll
            for (int ni = 0; ni < 8; ni++) {
                uint32_t off = sw128(lr * 128 + ni * 16 + (l & 3) * 4);
                *(uint32_t*)(smem + (PB - sb) + off) =
                    pack_h2(sc[mi][ni][rr * 2], sc[mi][ni][rr * 2 + 1]);
            }
        }
    __syncwarp();

    float o[2][4][4];
    #pragma unroll
    for (int mi = 0; mi < 2; mi++)
        #pragma unroll
        for (int nj = 0; nj < 4; nj++)
            #pragma unroll
            for (int r = 0; r < 4; r++) o[mi][nj][r] = 0.f;

    #pragma unroll
    for (int k16 = 0; k16 < 4; k16++) {
        uint32_t P[2][4];
        #pragma unroll
        for (int mi = 0; mi < 2; mi++) {
            uint32_t r = (mi * 16 + arl) * 128 + k16 * 32 + acb;
            ldsm4(P[mi], PB + sw128(r));
        }
        #pragma unroll
        for (int nj = 0; nj < 4; nj++) {
            uint32_t V[2];
            uint32_t r = (k16 * 16 + lb) * 128 + hl * 64 + nj * 16;
            ldsm2t(V, VB + sw128(r));
            #pragma unroll
            for (int mi = 0; mi < 2; mi++)
                mma16816(o[mi][nj], P[mi], V);
        }
    }

    const int head = hg * 2 + hl;
    #pragma unroll
    for (int mi = 0; mi < 2; mi++)
        #pragma unroll
        for (int rr = 0; rr < 2; rr++) {
            int r = w * 32 + mi * 16 + rr * 8 + (l >> 2);
            float inv = rinv[mi][rr];
            size_t rowoff = (size_t)(win * 64 + r) * CDIM + head * 32;
            #pragma unroll
            for (int nj = 0; nj < 4; nj++) {
                int c = nj * 8 + (l & 3) * 2;
                *(uint32_t*)(g_att_f16 + rowoff + c) =
                    pack_h2(o[mi][nj][rr * 2] * inv, o[mi][nj][rr * 2 + 1] * inv);
            }
        }
}

// ---------------------------------------------------------------------------
extern "C" void kernel_launch(void* const* d_in, const int* in_sizes, int n_in,
                              void* d_out, int out_size) {
    const float* x     = (const float*)d_in[0];
    const float* w_qkv = (const float*)d_in[1];
    const float* b_qkv = (const float*)d_in[2];
    const float* w_out = (const float*)d_in[3];
    const float* b_out = (const float*)d_in[4];
    const float* pos   = (const float*)d_in[5];
    float* out = (float*)d_out;

    __half *qkv, *xf, *af, *wq, *wo;
    cudaGetSymbolAddress((void**)&qkv, g_qkv_f16);
    cudaGetSymbolAddress((void**)&xf,  g_x_f16);
    cudaGetSymbolAddress((void**)&af,  g_att_f16);
    cudaGetSymbolAddress((void**)&wq,  g_wq);
    cudaGetSymbolAddress((void**)&wo,  g_wo);

    cudaFuncSetAttribute(gemm_mma<QKV_N, false, true>,
                         cudaFuncAttributeMaxDynamicSharedMemorySize, SMEM_GEMM);
    cudaFuncSetAttribute(gemm_mma<CDIM, true, false>,
                         cudaFuncAttributeMaxDynamicSharedMemorySize, SMEM_GEMM);
    cudaFuncSetAttribute(attn_mma,
                         cudaFuncAttributeMaxDynamicSharedMemorySize, SMEM_ATT);

    convert_w<<<1024, 256>>>(w_qkv, w_out);
    build_bias<<<32, 256>>>(pos);
    convert_x<<<NWIN, 256>>>(x);
    gemm_mma<QKV_N, false, true><<<dim3(6, 2048), 128, SMEM_GEMM>>>(
        xf, wq, b_qkv, nullptr, qkv);
    attn_mma<<<dim3(4, NWIN), 128, SMEM_ATT>>>(qkv);
    gemm_mma<CDIM, true, false><<<dim3(2, 2048), 128, SMEM_GEMM>>>(
        af, wo, b_out, out, nullptr);
}

// round 11
// speedup vs baseline: 2.4719x; 1.0115x over previous
#include <cuda_runtime.h>
#include <cuda_fp16.h>
#include <math.h>
#include <stdint.h>

// Problem constants
#define BATCH   32
#define HDIM    64
#define WDIM    64
#define CDIM    256
#define WS      8
#define SS      4
#define HEADS   8
#define HD      32
#define WS2     64
#define NWPI    64
#define NWIN    2048
#define QKV_N   768
#define MROWS   (NWIN * WS2)          // 131072
#define SCALE   0.17677669529663687f

// Scratch (all fp16)
__device__ __half g_qkv_f16[(size_t)MROWS * QKV_N];
__device__ __half g_x_f16[(size_t)MROWS * CDIM];            // window-ordered
__device__ __half g_att_f16[(size_t)MROWS * CDIM];
__device__ __half g_wq[QKV_N * CDIM];                       // [n][k]
__device__ __half g_wo[CDIM * CDIM];
__device__ float g_bias[HEADS * 4 * WS2 * WS2];             // bias+mask per window class

// GEMM smem: 3 stages x {A 8K, B 16K}
#define STAGE_BYTES 24576
#define SOFF_B      8192
#define OFF_BIAS    73728
#define SMEM_GEMM   74240

// Attention smem: Q 8K | K 8K | V 8K  (Q/K reused for P)
#define SMEM_ATT    24576

__device__ __forceinline__ int global_row(int win, int m) {
    int b  = win >> 6;
    int wi = win & 63;
    int wy = wi >> 3, wx = wi & 7;
    int ty = m >> 3,  tx = m & 7;
    int sy = (wy * 8 + ty + SS) & 63;
    int sx = (wx * 8 + tx + SS) & 63;
    return b * (HDIM * WDIM) + sy * WDIM + sx;
}

__device__ __forceinline__ uint32_t smem_u32(const void* p) {
    uint32_t a;
    asm("{ .reg .u64 t; cvta.to.shared.u64 t, %1; cvt.u32.u64 %0, t; }" : "=r"(a) : "l"(p));
    return a;
}
__device__ __forceinline__ uint32_t sw128(uint32_t off) {
    return off ^ ((off >> 3) & 0x70);
}
__device__ __forceinline__ void cp16(uint32_t dst, const void* src) {
    asm volatile("cp.async.cg.shared.global [%0], [%1], 16;" :: "r"(dst), "l"(src));
}
__device__ __forceinline__ void ldsm4(uint32_t* r, uint32_t addr) {
    asm volatile("ldmatrix.sync.aligned.m8n8.x4.shared.b16 {%0,%1,%2,%3}, [%4];"
                 : "=r"(r[0]), "=r"(r[1]), "=r"(r[2]), "=r"(r[3]) : "r"(addr));
}
__device__ __forceinline__ void ldsm2(uint32_t* r, uint32_t addr) {
    asm volatile("ldmatrix.sync.aligned.m8n8.x2.shared.b16 {%0,%1}, [%2];"
                 : "=r"(r[0]), "=r"(r[1]) : "r"(addr));
}
__device__ __forceinline__ void ldsm2t(uint32_t* r, uint32_t addr) {
    asm volatile("ldmatrix.sync.aligned.m8n8.x2.trans.shared.b16 {%0,%1}, [%2];"
                 : "=r"(r[0]), "=r"(r[1]) : "r"(addr));
}
__device__ __forceinline__ void mma16816(float* c, const uint32_t* a, const uint32_t* b) {
    asm volatile(
        "mma.sync.aligned.m16n8k16.row.col.f32.f16.f16.f32 "
        "{%0,%1,%2,%3}, {%4,%5,%6,%7}, {%8,%9}, {%0,%1,%2,%3};"
        : "+f"(c[0]), "+f"(c[1]), "+f"(c[2]), "+f"(c[3])
        : "r"(a[0]), "r"(a[1]), "r"(a[2]), "r"(a[3]), "r"(b[0]), "r"(b[1]));
}

__device__ __forceinline__ uint32_t pack_h2(float a, float b) {
    __half2 h = __floats2half2_rn(a, b);
    return *(uint32_t*)&h;
}

// ---------------------------------------------------------------------------
// 64x128-tile single-pass fp16 HMMA GEMM. 128 threads = 4 warps (2m x 2n),
// warp tile 32x64. 3-stage cp.async ring (wait_group 1), grid = (nb, mt).
// ---------------------------------------------------------------------------
template<int NT, bool SCATTER, bool OUTF16>
__global__ __launch_bounds__(128, 3) void gemm_mma(
    const __half* __restrict__ Af, const __half* __restrict__ Bf,
    const float* __restrict__ bias, float* __restrict__ out,
    __half* __restrict__ oh)
{
    extern __shared__ char smem[];
    const uint32_t sb = smem_u32(smem);
    const int tid = threadIdx.x, l = tid & 31, wid = tid >> 5;
    const int nb = blockIdx.x, mt = blockIdx.y;
    const int wm = wid >> 1, wn = wid & 1;

    float* bias_s = (float*)(smem + OFF_BIAS);
    bias_s[tid] = bias[nb * 128 + tid];

    // cp.async geometry: chunk row = (tid>>3) + i*16, 16B chunk (tid&7)
    const int crow = tid >> 3;
    const int cc   = tid & 7;
    uint32_t smo[8];
    #pragma unroll
    for (int i = 0; i < 8; i++)
        smo[i] = sw128((crow + i * 16) * 128 + cc * 16);

    const __half* pA = Af + (size_t)(mt * 64 + crow) * CDIM + cc * 8;
    const __half* pB = Bf + (size_t)(nb * 128 + crow) * CDIM + cc * 8;

    // ldmatrix lane geometry
    const int sub = l >> 3;
    const int arl = wm * 32 + (sub & 1) * 8 + (l & 7);  // A row (+mi*16)
    const int acb = (sub >> 1) * 16;                    // A col byte (+k0b)
    const int brl = ((l >> 4) << 3) + (l & 7);          // B row within n16 (+njj*16)
    const int bcb = ((l >> 3) & 1) * 16;                // B col byte (+k0b)

    float acc[2][8][4];
    #pragma unroll
    for (int i = 0; i < 2; i++)
        #pragma unroll
        for (int j = 0; j < 8; j++)
            #pragma unroll
            for (int r = 0; r < 4; r++) acc[i][j][r] = 0.f;

    // prologue: prefetch chunks 0 and 1 into stages 0 and 1
    #pragma unroll
    for (int c = 0; c < 2; c++) {
        uint32_t buf = sb + c * STAGE_BYTES;
        int ko = c * 64;
        #pragma unroll
        for (int i = 0; i < 4; i++)
            cp16(buf + smo[i], pA + (size_t)(i * 16) * CDIM + ko);
        #pragma unroll
        for (int i = 0; i < 8; i++)
            cp16(buf + SOFF_B + smo[i], pB + (size_t)(i * 16) * CDIM + ko);
        asm volatile("cp.async.commit_group;");
    }

    #pragma unroll
    for (int k = 0; k < 4; k++) {
        // chunk k ready when <=1 groups outstanding (k<3); last chunk: drain all
        if (k < 3) asm volatile("cp.async.wait_group 1;");
        else       asm volatile("cp.async.wait_group 0;");
        __syncthreads();   // also guarantees buffer (k+2)%3 is no longer being read

        if (k + 2 < 4) {
            uint32_t buf = sb + ((k + 2) % 3) * STAGE_BYTES;
            int ko = (k + 2) * 64;
            #pragma unroll
            for (int i = 0; i < 4; i++)
                cp16(buf + smo[i], pA + (size_t)(i * 16) * CDIM + ko);
            #pragma unroll
            for (int i = 0; i < 8; i++)
                cp16(buf + SOFF_B + smo[i], pB + (size_t)(i * 16) * CDIM + ko);
            asm volatile("cp.async.commit_group;");
        }

        const uint32_t cb = sb + (k % 3) * STAGE_BYTES;
        #pragma unroll
        for (int k16 = 0; k16 < 4; k16++) {
            const int k0b = k16 * 32;
            // B: 4x ldsm4, each covers n16 x k16 (2 MMA B-frags)
            uint32_t Bf2[8][2];
            #pragma unroll
            for (int njj = 0; njj < 4; njj++) {
                uint32_t r4[4];
                uint32_t r = (wn * 64 + njj * 16 + brl) * 128 + k0b + bcb;
                ldsm4(r4, cb + SOFF_B + sw128(r));
                Bf2[njj * 2][0]     = r4[0];
                Bf2[njj * 2][1]     = r4[1];
                Bf2[njj * 2 + 1][0] = r4[2];
                Bf2[njj * 2 + 1][1] = r4[3];
            }
            #pragma unroll
            for (int mi = 0; mi < 2; mi++) {
                uint32_t r = (arl + mi * 16) * 128 + k0b + acb;
                uint32_t Afr[4];
                ldsm4(Afr, cb + sw128(r));
                #pragma unroll
                for (int ni = 0; ni < 8; ni++)
                    mma16816(acc[mi][ni], Afr, Bf2[ni]);
            }
        }
    }
    __syncthreads();

    // epilogue via smem stage (64 x 132 floats)
    float* stage = (float*)smem;
    #pragma unroll
    for (int mi = 0; mi < 2; mi++)
        #pragma unroll
        for (int ni = 0; ni < 8; ni++) {
            int r   = wm * 32 + mi * 16 + (l >> 2);
            int col = wn * 64 + ni * 8 + (l & 3) * 2;
            *(float2*)&stage[r * 132 + col]       = make_float2(acc[mi][ni][0], acc[mi][ni][1]);
            *(float2*)&stage[(r + 8) * 132 + col] = make_float2(acc[mi][ni][2], acc[mi][ni][3]);
        }
    __syncthreads();

    #pragma unroll
    for (int it = 0; it < 16; it++) {
        int idx = it * 128 + tid;
        int r  = idx >> 5, c4 = (idx & 31) * 4;
        float4 o;
        o.x = stage[r * 132 + c4 + 0] + bias_s[c4 + 0];
        o.y = stage[r * 132 + c4 + 1] + bias_s[c4 + 1];
        o.z = stage[r * 132 + c4 + 2] + bias_s[c4 + 2];
        o.w = stage[r * 132 + c4 + 3] + bias_s[c4 + 3];
        int lrow = mt * 64 + r;
        int orow = SCATTER ? global_row(lrow >> 6, lrow & 63) : lrow;
        size_t off = (size_t)orow * NT + nb * 128 + c4;
        if (OUTF16) {
            *(uint2*)(oh + off) = make_uint2(pack_h2(o.x, o.y), pack_h2(o.z, o.w));
        } else {
            *(float4*)(out + off) = o;
        }
    }
}

// ---------------------------------------------------------------------------
// Pre-pass: gather x into window order, convert to fp16
// ---------------------------------------------------------------------------
__global__ __launch_bounds__(256) void convert_x(const float* __restrict__ x) {
    const int win = blockIdx.x;
    const int tid = threadIdx.x;
    #pragma unroll
    for (int i = 0; i < 16; i++) {
        int idx4 = i * 256 + tid;
        int row  = idx4 >> 6;
        int c4   = idx4 & 63;
        int grow = global_row(win, row);
        float4 v = *(const float4*)(x + (size_t)grow * CDIM + c4 * 4);
        size_t o = ((size_t)win * WS2 + row) * CDIM + c4 * 4;
        *(uint2*)(g_x_f16 + o) = make_uint2(pack_h2(v.x, v.y), pack_h2(v.z, v.w));
    }
}

__global__ void convert_w(const float* __restrict__ wq, const float* __restrict__ wo) {
    int n = blockIdx.x, k = threadIdx.x;
    if (n < QKV_N) {
        g_wq[n * CDIM + k] = __float2half_rn(wq[k * QKV_N + n]);
    } else {
        int n2 = n - QKV_N;
        g_wo[n2 * CDIM + k] = __float2half_rn(wo[k * CDIM + n2]);
    }
}

// ---------------------------------------------------------------------------
// Build bias+mask table: [head][class][64q][64k]
// ---------------------------------------------------------------------------
__global__ void build_bias(const float* __restrict__ pos) {
    int h = blockIdx.x >> 2, cls = blockIdx.x & 3;
    int wy = (cls & 2) ? 7 : 0, wx = (cls & 1) ? 7 : 0;
    for (int it = 0; it < 16; it++) {
        int idx = it * 256 + threadIdx.x;
        int q = idx >> 6, k = idx & 63;
        int qy = q >> 3, qx = q & 7, ky = k >> 3, kx = k & 7;
        int gy = wy * 8 + qy, gx = wx * 8 + qx;
        int hy = wy * 8 + ky, hx = wx * 8 + kx;
        int rq = (gy < 56 ? 0 : (gy < 60 ? 1 : 2)) * 3 + (gx < 56 ? 0 : (gx < 60 ? 1 : 2));
        int rk = (hy < 56 ? 0 : (hy < 60 ? 1 : 2)) * 3 + (hx < 56 ? 0 : (hx < 60 ? 1 : 2));
        float v = (rq == rk) ? pos[h * 225 + (qy - ky + 7) * 15 + (qx - kx + 7)] : -1e30f;
        g_bias[(size_t)(h * 4 + cls) * 4096 + idx] = v;
    }
}

// ---------------------------------------------------------------------------
// fp16 HMMA attention. Block = (2 heads, window), 4 warps; warp = 32q x 64k.
// ---------------------------------------------------------------------------
__global__ __launch_bounds__(128) void attn_mma(const __half* __restrict__ qkv)
{
    extern __shared__ char smem[];
    const uint32_t sb = smem_u32(smem);
    const int tid = threadIdx.x, l = tid & 31, wid = tid >> 5;
    const int hg  = blockIdx.x;
    const int win = blockIdx.y;
    const int wi  = win & 63, wy = wi >> 3, wx = wi & 7;
    const int cls = ((wy == 7) ? 2 : 0) | ((wx == 7) ? 1 : 0);

    #pragma unroll
    for (int i = 0; i < 12; i++) {
        int idx  = i * 128 + tid;
        int mat  = idx >> 9;
        int rem  = idx & 511;
        int row  = rem >> 3;
        int ch   = rem & 7;
        int hsel = ch >> 2;
        int c16  = ch & 3;
        uint32_t dst = sb + mat * 8192 + sw128(row * 128 + hsel * 64 + c16 * 16);
        const __half* src = qkv + (size_t)(win * 64 + row) * QKV_N
                          + (hg * 2 + hsel) * 32 + mat * 256 + c16 * 8;
        cp16(dst, src);
    }
    asm volatile("cp.async.commit_group;");
    asm volatile("cp.async.wait_group 0;");
    __syncthreads();

    const int hl = wid >> 1;
    const int w  = wid & 1;
    const uint32_t QB = sb;
    const uint32_t KB = sb + 8192;
    const uint32_t VB = sb + 16384;
    const float* T = g_bias + (size_t)((hg * 2 + hl) * 4 + cls) * 4096;

    const int sub = l >> 3;
    const int arl = (sub & 1) * 8 + (l & 7);
    const int acb = (sub >> 1) * 16;
    const int lb  = l & 15;
    const int brl = lb & 7;
    const int bcb = (lb >> 3) * 16;

    float sc[2][8][4];
    #pragma unroll
    for (int mi = 0; mi < 2; mi++)
        #pragma unroll
        for (int ni = 0; ni < 8; ni++)
            #pragma unroll
            for (int r = 0; r < 4; r++) sc[mi][ni][r] = 0.f;

    #pragma unroll
    for (int k16 = 0; k16 < 2; k16++) {
        uint32_t A[2][4];
        #pragma unroll
        for (int mi = 0; mi < 2; mi++) {
            uint32_t r = (w * 32 + mi * 16 + arl) * 128 + hl * 64 + k16 * 32 + acb;
            ldsm4(A[mi], QB + sw128(r));
        }
        #pragma unroll
        for (int ni = 0; ni < 8; ni++) {
            uint32_t B[2];
            uint32_t r = (ni * 8 + brl) * 128 + hl * 64 + k16 * 32 + bcb;
            ldsm2(B, KB + sw128(r));
            #pragma unroll
            for (int mi = 0; mi < 2; mi++)
                mma16816(sc[mi][ni], A[mi], B);
        }
    }

    float rinv[2][2];
    #pragma unroll
    for (int mi = 0; mi < 2; mi++)
        #pragma unroll
        for (int rr = 0; rr < 2; rr++) {
            int r = w * 32 + mi * 16 + rr * 8 + (l >> 2);
            const float* Tr = T + r * 64 + (l & 3) * 2;
            float m = -1e30f;
            #pragma unroll
            for (int ni = 0; ni < 8; ni++) {
                float2 b2 = *(const float2*)(Tr + ni * 8);
                float v0 = sc[mi][ni][rr * 2]     * SCALE + b2.x;
                float v1 = sc[mi][ni][rr * 2 + 1] * SCALE + b2.y;
                sc[mi][ni][rr * 2]     = v0;
                sc[mi][ni][rr * 2 + 1] = v1;
                m = fmaxf(m, fmaxf(v0, v1));
            }
            m = fmaxf(m, __shfl_xor_sync(0xffffffffu, m, 1));
            m = fmaxf(m, __shfl_xor_sync(0xffffffffu, m, 2));
            float s = 0.f;
            #pragma unroll
            for (int ni = 0; ni < 8; ni++)
                #pragma unroll
                for (int j = 0; j < 2; j++) {
                    float e = __expf(sc[mi][ni][rr * 2 + j] - m);
                    sc[mi][ni][rr * 2 + j] = e;
                    s += e;
                }
            s += __shfl_xor_sync(0xffffffffu, s, 1);
            s += __shfl_xor_sync(0xffffffffu, s, 2);
            rinv[mi][rr] = 1.0f / s;
        }

    __syncthreads();

    const uint32_t PB = sb + (hl * 2 + w) * 4096;
    #pragma unroll
    for (int mi = 0; mi < 2; mi++)
        #pragma unroll
        for (int rr = 0; rr < 2; rr++) {
            int lr = mi * 16 + rr * 8 + (l >> 2);
            #pragma unroll
            for (int ni = 0; ni < 8; ni++) {
                uint32_t off = sw128(lr * 128 + ni * 16 + (l & 3) * 4);
                *(uint32_t*)(smem + (PB - sb) + off) =
                    pack_h2(sc[mi][ni][rr * 2], sc[mi][ni][rr * 2 + 1]);
            }
        }
    __syncwarp();

    float o[2][4][4];
    #pragma unroll
    for (int mi = 0; mi < 2; mi++)
        #pragma unroll
        for (int nj = 0; nj < 4; nj++)
            #pragma unroll
            for (int r = 0; r < 4; r++) o[mi][nj][r] = 0.f;

    #pragma unroll
    for (int k16 = 0; k16 < 4; k16++) {
        uint32_t P[2][4];
        #pragma unroll
        for (int mi = 0; mi < 2; mi++) {
            uint32_t r = (mi * 16 + arl) * 128 + k16 * 32 + acb;
            ldsm4(P[mi], PB + sw128(r));
        }
        #pragma unroll
        for (int nj = 0; nj < 4; nj++) {
            uint32_t V[2];
            uint32_t r = (k16 * 16 + lb) * 128 + hl * 64 + nj * 16;
            ldsm2t(V, VB + sw128(r));
            #pragma unroll
            for (int mi = 0; mi < 2; mi++)
                mma16816(o[mi][nj], P[mi], V);
        }
    }

    const int head = hg * 2 + hl;
    #pragma unroll
    for (int mi = 0; mi < 2; mi++)
        #pragma unroll
        for (int rr = 0; rr < 2; rr++) {
            int r = w * 32 + mi * 16 + rr * 8 + (l >> 2);
            float inv = rinv[mi][rr];
            size_t rowoff = (size_t)(win * 64 + r) * CDIM + head * 32;
            #pragma unroll
            for (int nj = 0; nj < 4; nj++) {
                int c = nj * 8 + (l & 3) * 2;
                *(uint32_t*)(g_att_f16 + rowoff + c) =
                    pack_h2(o[mi][nj][rr * 2] * inv, o[mi][nj][rr * 2 + 1] * inv);
            }
        }
}

// ---------------------------------------------------------------------------
extern "C" void kernel_launch(void* const* d_in, const int* in_sizes, int n_in,
                              void* d_out, int out_size) {
    const float* x     = (const float*)d_in[0];
    const float* w_qkv = (const float*)d_in[1];
    const float* b_qkv = (const float*)d_in[2];
    const float* w_out = (const float*)d_in[3];
    const float* b_out = (const float*)d_in[4];
    const float* pos   = (const float*)d_in[5];
    float* out = (float*)d_out;

    __half *qkv, *xf, *af, *wq, *wo;
    cudaGetSymbolAddress((void**)&qkv, g_qkv_f16);
    cudaGetSymbolAddress((void**)&xf,  g_x_f16);
    cudaGetSymbolAddress((void**)&af,  g_att_f16);
    cudaGetSymbolAddress((void**)&wq,  g_wq);
    cudaGetSymbolAddress((void**)&wo,  g_wo);

    cudaFuncSetAttribute(gemm_mma<QKV_N, false, true>,
                         cudaFuncAttributeMaxDynamicSharedMemorySize, SMEM_GEMM);
    cudaFuncSetAttribute(gemm_mma<CDIM, true, false>,
                         cudaFuncAttributeMaxDynamicSharedMemorySize, SMEM_GEMM);
    cudaFuncSetAttribute(attn_mma,
                         cudaFuncAttributeMaxDynamicSharedMemorySize, SMEM_ATT);

    convert_w<<<1024, 256>>>(w_qkv, w_out);
    build_bias<<<32, 256>>>(pos);
    convert_x<<<NWIN, 256>>>(x);
    gemm_mma<QKV_N, false, true><<<dim3(6, 2048), 128, SMEM_GEMM>>>(
        xf, wq, b_qkv, nullptr, qkv);
    attn_mma<<<dim3(4, NWIN), 128, SMEM_ATT>>>(qkv);
    gemm_mma<CDIM, true, false><<<dim3(2, 2048), 128, SMEM_GEMM>>>(
        af, wo, b_out, out, nullptr);
}